// round 6
// baseline (speedup 1.0000x reference)
#include <cuda_runtime.h>
#include <cuda_bf16.h>
#include <cstdint>

#define DM 1024
#define DS 16
#define NB 4
#define LS 2048
#define MR (NB*LS)      // 8192 rows
#define LC 32           // scan chunk length
#define NCH (LS/LC)     // 64 chunks

// ---------------- scratch (device globals; no allocations) ----------------
__device__ __align__(256) int8_t g_xnq[MR*DM];           // quantized LN output
__device__ __align__(256) float  g_xs[MR];               // per-row dequant scale
__device__ __align__(256) int8_t g_w1q[2*DM*DM];         // quantized in_w
__device__ __align__(256) float  g_ws1[2*DM];            // per-out-channel scale
__device__ __align__(256) int8_t g_w2q[DM*DM];           // quantized out_w
__device__ __align__(256) float  g_ws2[DM];
__device__ __align__(256) __nv_bfloat16 g_xproj[MR*DM];  // ssm input u
__device__ __align__(256) __nv_bfloat16 g_zs[MR*DM];     // silu(z)
__device__ __align__(256) __nv_bfloat16 g_gated[MR*DM];  // y * silu(z) (bf16)
__device__ __align__(256) int8_t g_gatedq[MR*DM];        // quantized gated
__device__ __align__(256) float  g_gs[MR];               // per-row scale
__device__ __align__(256) float g_Abar[DM*DS];
__device__ __align__(256) float g_cbdt[DM*DS];
__device__ __align__(256) float g_Apow[DM*DS];           // Abar^LC
__device__ __align__(256) float g_F[NCH*NB*DM*DS];       // chunk-local end states
__device__ __align__(256) float g_Sin[NCH*NB*DM*DS];     // chunk incoming states

// ---------------- PTX helpers ----------------
__device__ __forceinline__ void cp16(uint32_t s, const void* g){
    asm volatile("cp.async.cg.shared.global [%0], [%1], 16;\n" :: "r"(s), "l"(g));
}
#define LDSM4(v, addr) \
    asm volatile("ldmatrix.sync.aligned.m8n8.x4.shared.b16 {%0,%1,%2,%3}, [%4];" \
        : "=r"((v)[0]), "=r"((v)[1]), "=r"((v)[2]), "=r"((v)[3]) : "r"(addr))
// int8 mma: m16n8k32, s8 x s8 -> s32. Byte-layout of fragments equals the
// validated bf16 k16 path viewed as b16 pairs, so LDSM4 addressing is reused.
#define MMAS8(d, a, b0, b1) \
    asm volatile("mma.sync.aligned.m16n8k32.row.col.s32.s8.s8.s32 " \
        "{%0,%1,%2,%3},{%4,%5,%6,%7},{%8,%9},{%0,%1,%2,%3};" \
        : "+r"((d)[0]), "+r"((d)[1]), "+r"((d)[2]), "+r"((d)[3]) \
        : "r"((a)[0]), "r"((a)[1]), "r"((a)[2]), "r"((a)[3]), "r"(b0), "r"(b1))

__device__ __forceinline__ float blk_absmax(float m, int t){
    #pragma unroll
    for(int o = 16; o; o >>= 1) m = fmaxf(m, __shfl_xor_sync(0xffffffffu, m, o));
    __shared__ float ms[8];
    int w = t >> 5, lane = t & 31;
    if(lane == 0) ms[w] = m;
    __syncthreads();
    m = 0.f;
    #pragma unroll
    for(int i = 0; i < 8; i++) m = fmaxf(m, ms[i]);
    return fmaxf(m, 1e-10f);
}
__device__ __forceinline__ int8_t q8(float v, float qs){
    return (int8_t)__float2int_rn(v * qs);
}

// ---------------- prep: per-row weight quantization ----------------
__global__ void prep_w(const float* __restrict__ in_w, const float* __restrict__ out_w){
    int r = blockIdx.x, t = threadIdx.x;
    const float* src = (r < 2*DM) ? in_w + (size_t)r*DM : out_w + (size_t)(r - 2*DM)*DM;
    float4 v = reinterpret_cast<const float4*>(src)[t];
    float m = fmaxf(fmaxf(fabsf(v.x), fabsf(v.y)), fmaxf(fabsf(v.z), fabsf(v.w)));
    m = blk_absmax(m, t);
    float qs = 127.f / m;
    char4 q; q.x = q8(v.x, qs); q.y = q8(v.y, qs); q.z = q8(v.z, qs); q.w = q8(v.w, qs);
    if(r < 2*DM){
        *reinterpret_cast<char4*>(&g_w1q[(size_t)r*DM + 4*t]) = q;
        if(t == 0) g_ws1[r] = m / 127.f;
    } else {
        *reinterpret_cast<char4*>(&g_w2q[(size_t)(r - 2*DM)*DM + 4*t]) = q;
        if(t == 0) g_ws2[r - 2*DM] = m / 127.f;
    }
}

// ---------------- prep: SSM params ----------------
__global__ void prep_ssm(const float* __restrict__ A_log, const float* __restrict__ Bp,
                         const float* __restrict__ Cp, const float* __restrict__ log_dt){
    int j = blockIdx.x*blockDim.x + threadIdx.x;   // over DM*DS
    int d = j >> 4;
    float dt = fminf(fmaxf(expf(log_dt[d]), 1e-4f), 1.0f);
    float Ab = expf(-expf(A_log[j]) * dt);
    Ab = fminf(fmaxf(Ab, 1e-8f), 1.0f - 1e-8f);
    g_Abar[j] = Ab;
    g_cbdt[j] = Cp[j] * Bp[j] * dt;
    float p = Ab;
    #pragma unroll
    for(int q = 0; q < 5; q++) p = p*p;            // Abar^32 (LC=32)
    g_Apow[j] = p;
}

// ---------------- layernorm + fused int8 quant (row = one block) -------------
__global__ void ln_kernel(const float* __restrict__ x, const float* __restrict__ g,
                          const float* __restrict__ b){
    int r = blockIdx.x, t = threadIdx.x;
    float4 v = reinterpret_cast<const float4*>(x + (size_t)r*DM)[t];
    float s = v.x+v.y+v.z+v.w;
    float q = v.x*v.x + v.y*v.y + v.z*v.z + v.w*v.w;
    #pragma unroll
    for(int o = 16; o; o >>= 1){
        s += __shfl_xor_sync(0xffffffffu, s, o);
        q += __shfl_xor_sync(0xffffffffu, q, o);
    }
    __shared__ float ss[8], qs_[8];
    int w = t >> 5, lane = t & 31;
    if(lane == 0){ ss[w] = s; qs_[w] = q; }
    __syncthreads();
    s = 0.f; q = 0.f;
    #pragma unroll
    for(int i = 0; i < 8; i++){ s += ss[i]; q += qs_[i]; }
    float mu  = s * (1.0f/DM);
    float var = q * (1.0f/DM) - mu*mu;
    float rs  = rsqrtf(var + 1e-5f);
    float4 gv = reinterpret_cast<const float4*>(g)[t];
    float4 bv = reinterpret_cast<const float4*>(b)[t];
    float o0 = (v.x-mu)*rs*gv.x + bv.x;
    float o1 = (v.y-mu)*rs*gv.y + bv.y;
    float o2 = (v.z-mu)*rs*gv.z + bv.z;
    float o3 = (v.w-mu)*rs*gv.w + bv.w;
    float m = fmaxf(fmaxf(fabsf(o0), fabsf(o1)), fmaxf(fabsf(o2), fabsf(o3)));
    __syncthreads();            // ss/qs_ still in flight; barrier before ms[] reuse
    m = blk_absmax(m, t);
    float qsc = 127.f / m;
    char4 qv; qv.x = q8(o0, qsc); qv.y = q8(o1, qsc); qv.z = q8(o2, qsc); qv.w = q8(o3, qsc);
    *reinterpret_cast<char4*>(&g_xnq[(size_t)r*DM + 4*t]) = qv;
    if(t == 0) g_xs[r] = m / 127.f;
}

// ---------------- per-row quant of gated activations ----------------
__global__ void quant_gated(){
    int r = blockIdx.x, t = threadIdx.x;
    uint2 pk = reinterpret_cast<const uint2*>(g_gated + (size_t)r*DM)[t];
    __nv_bfloat162 h0 = *(__nv_bfloat162*)&pk.x;
    __nv_bfloat162 h1 = *(__nv_bfloat162*)&pk.y;
    float f0 = __bfloat162float(h0.x), f1 = __bfloat162float(h0.y);
    float f2 = __bfloat162float(h1.x), f3 = __bfloat162float(h1.y);
    float m = fmaxf(fmaxf(fabsf(f0), fabsf(f1)), fmaxf(fabsf(f2), fabsf(f3)));
    m = blk_absmax(m, t);
    float qsc = 127.f / m;
    char4 qv; qv.x = q8(f0, qsc); qv.y = q8(f1, qsc); qv.z = q8(f2, qsc); qv.w = q8(f3, qsc);
    *reinterpret_cast<char4*>(&g_gatedq[(size_t)r*DM + 4*t]) = qv;
    if(t == 0) g_gs[r] = m / 127.f;
}

// ---------------- INT8 IMMA GEMM: C[M,N] = A[M,K] @ B[N,K]^T + epilogue ------
// CTA tile 128(M) x 256(N), 8 warps (64x64), K chunks of 64 int8,
// 3-stage cp.async pipeline, ldmatrix.x4 fragments, XOR-swizzled smem.
// MODE 0: xz = xn @ in_w^T * scales + in_b ; split + silu, bf16 out
// MODE 1: out = gated @ out_w^T * scales + out_b + resid, clip, fp32 out
#define STG_BYTES 24576          // 8KB A + 16KB B
#define GEMM_SMEM (3*STG_BYTES + 128)

template<int MODE>
__global__ void __launch_bounds__(256) gemm_s8(const float* __restrict__ bias,
                                               const float* __restrict__ resid,
                                               float* __restrict__ outp){
    constexpr int K = DM;        // bytes per row (1B/elem)
    const int8_t* __restrict__ Am = (MODE==0) ? g_xnq : g_gatedq;
    const int8_t* __restrict__ Bm = (MODE==0) ? g_w1q : g_w2q;
    const float*  __restrict__ sA = (MODE==0) ? g_xs  : g_gs;
    const float*  __restrict__ sB = (MODE==0) ? g_ws1 : g_ws2;

    extern __shared__ char smem_dyn[];
    uint32_t sbase = (uint32_t)__cvta_generic_to_shared(smem_dyn);
    sbase = (sbase + 127) & ~127u;

    int t = threadIdx.x, lane = t & 31, wid = t >> 5;
    int wm = wid >> 2, wn = wid & 3;             // 2 x 4 warps over 128x256
    int m0 = blockIdx.y * 128, n0 = blockIdx.x * 256;

    const char* gA = (const char*)Am + (size_t)m0 * K;
    const char* gB = (const char*)Bm + (size_t)n0 * K;

    auto load = [&](int k, int st){
        uint32_t sAo = sbase + (uint32_t)st*STG_BYTES;
        uint32_t sBo = sAo + 8192;
        int koff = k*64;                          // 64 int8 per chunk
        #pragma unroll
        for(int i = 0; i < 2; i++){               // A: 128 rows x 4 x 16B
            int ci = t + i*256;
            int r = ci >> 2, c = ci & 3;
            cp16(sAo + (uint32_t)(r*64 + ((c ^ ((r>>1)&3))<<4)),
                 gA + (size_t)r*K + koff + c*16);
        }
        #pragma unroll
        for(int i = 0; i < 4; i++){               // B: 256 rows x 4 x 16B
            int ci = t + i*256;
            int r = ci >> 2, c = ci & 3;
            cp16(sBo + (uint32_t)(r*64 + ((c ^ ((r>>1)&3))<<4)),
                 gB + (size_t)r*K + koff + c*16);
        }
    };

    int acc[4][8][4];
    #pragma unroll
    for(int i=0;i<4;i++)
    #pragma unroll
    for(int j=0;j<8;j++)
    #pragma unroll
    for(int q=0;q<4;q++) acc[i][j][q] = 0;

    load(0, 0); asm volatile("cp.async.commit_group;");
    load(1, 1); asm volatile("cp.async.commit_group;");

    int la_r = lane & 15, la_k = lane >> 4;
    uint32_t sw = (uint32_t)((la_r >> 1) & 3);
    uint32_t aoff = (uint32_t)((wm*64 + la_r) * 64);
    uint32_t boff = (uint32_t)((wn*64 + la_r) * 64);

    #pragma unroll 1
    for(int k = 0; k < K/64; k++){                // 16 chunks
        int st = k % 3;
        asm volatile("cp.async.wait_group 1;");
        __syncthreads();
        uint32_t smA = sbase + (uint32_t)st*STG_BYTES + aoff;
        uint32_t smB = sbase + (uint32_t)st*STG_BYTES + 8192 + boff;
        #pragma unroll
        for(int ks = 0; ks < 2; ks++){            // 2 x k32 int8
            uint32_t kx = (uint32_t)(((ks*2 + la_k) ^ sw) << 4);
            uint32_t a[4][4], b[4][4];
            #pragma unroll
            for(int mi = 0; mi < 4; mi++) LDSM4(a[mi], smA + mi*1024 + kx);
            #pragma unroll
            for(int ng = 0; ng < 4; ng++) LDSM4(b[ng], smB + ng*1024 + kx);
            #pragma unroll
            for(int mi = 0; mi < 4; mi++)
            #pragma unroll
            for(int ng = 0; ng < 4; ng++){
                MMAS8(acc[mi][2*ng],   a[mi], b[ng][0], b[ng][2]);
                MMAS8(acc[mi][2*ng+1], a[mi], b[ng][1], b[ng][3]);
            }
        }
        if(k + 2 < K/64) load(k + 2, (k + 2) % 3);
        asm volatile("cp.async.commit_group;");
    }

    // ---------------- epilogue (dequant + fused ops, direct stores) ----------
    int grp = lane >> 2, c2 = (lane & 3) * 2;
    #pragma unroll
    for(int mi = 0; mi < 4; mi++){
        int row = m0 + wm*64 + mi*16 + grp;
        float xs0 = __ldg(&sA[row]), xs1 = __ldg(&sA[row + 8]);
        #pragma unroll
        for(int ni = 0; ni < 8; ni++){
            int col = n0 + wn*64 + ni*8 + c2;
            float w0 = __ldg(&sB[col]), w1 = __ldg(&sB[col+1]);
            float b0 = __ldg(&bias[col]), b1 = __ldg(&bias[col+1]);
            #pragma unroll
            for(int h = 0; h < 2; h++){
                int rr = row + h*8;
                float xsf = h ? xs1 : xs0;
                float v0 = (float)acc[mi][ni][2*h+0] * (xsf*w0) + b0;
                float v1 = (float)acc[mi][ni][2*h+1] * (xsf*w1) + b1;
                if(MODE == 0){
                    if(n0 >= DM){
                        v0 = v0 / (1.f + __expf(-v0));
                        v1 = v1 / (1.f + __expf(-v1));
                        __nv_bfloat162 p = __floats2bfloat162_rn(v0, v1);
                        *(uint32_t*)&g_zs[(size_t)rr*DM + col - DM] = *(uint32_t*)&p;
                    } else {
                        __nv_bfloat162 p = __floats2bfloat162_rn(v0, v1);
                        *(uint32_t*)&g_xproj[(size_t)rr*DM + col] = *(uint32_t*)&p;
                    }
                } else {
                    float2 rv = *(const float2*)&resid[(size_t)rr*DM + col];
                    v0 = fminf(fmaxf(v0 + rv.x, -10.f), 10.f);
                    v1 = fminf(fmaxf(v1 + rv.y, -10.f), 10.f);
                    float2 ov; ov.x = v0; ov.y = v1;
                    *(float2*)&outp[(size_t)rr*DM + col] = ov;
                }
            }
        }
    }
}

// ---------------- SSM chunked scan ----------------
__global__ void ssm_pass1(){
    int d = blockIdx.x*blockDim.x + threadIdx.x;
    int c = blockIdx.y, b = blockIdx.z;
    float Aa[DS];
    const float4* A4 = reinterpret_cast<const float4*>(g_Abar + d*DS);
    #pragma unroll
    for(int j=0;j<4;j++){ float4 v=A4[j]; Aa[4*j]=v.x; Aa[4*j+1]=v.y; Aa[4*j+2]=v.z; Aa[4*j+3]=v.w; }
    float s[DS];
    #pragma unroll
    for(int n=0;n<DS;n++) s[n] = 0.f;
    const __nv_bfloat16* u = g_xproj + (size_t)(b*LS + c*LC)*DM + d;
    #pragma unroll 4
    for(int tt = 0; tt < LC; ++tt){
        float uv = __bfloat162float(u[(size_t)tt*DM]);
        #pragma unroll
        for(int n=0;n<DS;n++) s[n] = fmaf(Aa[n], s[n], uv);
    }
    float4* F4 = reinterpret_cast<float4*>(g_F + (size_t)((c*NB + b)*DM + d)*DS);
    #pragma unroll
    for(int j=0;j<4;j++){ float4 v; v.x=s[4*j]; v.y=s[4*j+1]; v.z=s[4*j+2]; v.w=s[4*j+3]; F4[j]=v; }
}

__global__ void ssm_pass2(){
    int i = blockIdx.x*blockDim.x + threadIdx.x;      // over NB*DM*DS = 65536
    float Ap = g_Apow[i & (DM*DS - 1)];
    float s = 0.f;
    #pragma unroll 8
    for(int c = 0; c < NCH; c++){
        g_Sin[c*(NB*DM*DS) + i] = s;
        s = fmaf(Ap, s, g_F[c*(NB*DM*DS) + i]);
    }
}

__global__ void ssm_pass3(){
    int d = blockIdx.x*blockDim.x + threadIdx.x;
    int c = blockIdx.y, b = blockIdx.z;
    float Aa[DS], cb[DS], s[DS];
    const float4* A4 = reinterpret_cast<const float4*>(g_Abar + d*DS);
    const float4* C4 = reinterpret_cast<const float4*>(g_cbdt + d*DS);
    const float4* S4 = reinterpret_cast<const float4*>(g_Sin + (size_t)c*(NB*DM*DS) + (size_t)(b*DM + d)*DS);
    #pragma unroll
    for(int j=0;j<4;j++){
        float4 va=A4[j]; Aa[4*j]=va.x; Aa[4*j+1]=va.y; Aa[4*j+2]=va.z; Aa[4*j+3]=va.w;
        float4 vc=C4[j]; cb[4*j]=vc.x; cb[4*j+1]=vc.y; cb[4*j+2]=vc.z; cb[4*j+3]=vc.w;
        float4 vs=S4[j]; s[4*j]=vs.x;  s[4*j+1]=vs.y;  s[4*j+2]=vs.z;  s[4*j+3]=vs.w;
    }
    size_t base = (size_t)(b*LS + c*LC)*DM + d;
    const __nv_bfloat16* u  = g_xproj + base;
    const __nv_bfloat16* zp = g_zs    + base;
    __nv_bfloat16*       gp = g_gated + base;
    #pragma unroll 2
    for(int tt = 0; tt < LC; ++tt){
        float uv = __bfloat162float(u[(size_t)tt*DM]);
        #pragma unroll
        for(int n=0;n<DS;n++) s[n] = fmaf(Aa[n], s[n], uv);
        float y = 0.f;
        #pragma unroll
        for(int n=0;n<DS;n++) y = fmaf(cb[n], s[n], y);
        float zv = __bfloat162float(zp[(size_t)tt*DM]);
        gp[(size_t)tt*DM] = __float2bfloat16_rn(y * zv);
    }
}

// ---------------- launch ----------------
extern "C" void kernel_launch(void* const* d_in, const int* in_sizes, int n_in,
                              void* d_out, int out_size){
    const float* x      = (const float*)d_in[0];
    const float* A_log  = (const float*)d_in[1];
    const float* Bp     = (const float*)d_in[2];
    const float* Cp     = (const float*)d_in[3];
    const float* log_dt = (const float*)d_in[4];
    const float* in_w   = (const float*)d_in[5];
    const float* in_b   = (const float*)d_in[6];
    const float* out_w  = (const float*)d_in[7];
    const float* out_b  = (const float*)d_in[8];
    const float* ln_g   = (const float*)d_in[9];
    const float* ln_b   = (const float*)d_in[10];
    float* outp = (float*)d_out;

    cudaFuncSetAttribute(gemm_s8<0>, cudaFuncAttributeMaxDynamicSharedMemorySize, GEMM_SMEM);
    cudaFuncSetAttribute(gemm_s8<1>, cudaFuncAttributeMaxDynamicSharedMemorySize, GEMM_SMEM);

    prep_w<<<3*DM, 256>>>(in_w, out_w);
    prep_ssm<<<(DM*DS)/256, 256>>>(A_log, Bp, Cp, log_dt);
    ln_kernel<<<MR, 256>>>(x, ln_g, ln_b);
    gemm_s8<0><<<dim3(2*DM/256, MR/128), 256, GEMM_SMEM>>>(in_b, nullptr, nullptr);
    ssm_pass1<<<dim3(DM/128, NCH, NB), 128>>>();
    ssm_pass2<<<(NB*DM*DS)/256, 256>>>();
    ssm_pass3<<<dim3(DM/128, NCH, NB), 128>>>();
    quant_gated<<<MR, 256>>>();
    gemm_s8<1><<<dim3(DM/256, MR/128), 256, GEMM_SMEM>>>(out_b, x, outp);
}

// round 7
// speedup vs baseline: 3.2945x; 3.2945x over previous
#include <cuda_runtime.h>
#include <cuda_bf16.h>
#include <cstdint>

#define DM 1024
#define DS 16
#define NB 4
#define LS 2048
#define MR (NB*LS)      // 8192 rows
#define LC 32           // scan chunk length
#define NCH (LS/LC)     // 64 chunks

// ---------------- scratch (device globals; no allocations) ----------------
__device__ __align__(256) __nv_bfloat16 g_xn[MR*DM];     // layernormed x (bf16)
__device__ __align__(256) __nv_bfloat16 g_w1[2*DM*DM];   // in_w bf16
__device__ __align__(256) __nv_bfloat16 g_w2[DM*DM];     // out_w bf16
__device__ __align__(256) __nv_bfloat16 g_xproj[MR*DM];  // ssm input u
__device__ __align__(256) __nv_bfloat16 g_zs[MR*DM];     // silu(z)
__device__ __align__(256) __nv_bfloat16 g_gated[MR*DM];  // y * silu(z)
__device__ __align__(256) float g_Abar[DM*DS];
__device__ __align__(256) float g_cbdt[DM*DS];
__device__ __align__(256) float g_Apow[DM*DS];           // Abar^LC
__device__ __align__(256) float g_F[NCH*NB*DM*DS];       // chunk-local end states
__device__ __align__(256) float g_Sin[NCH*NB*DM*DS];     // chunk incoming states

// ---------------- PTX helpers ----------------
__device__ __forceinline__ void cp16(uint32_t s, const void* g){
    asm volatile("cp.async.cg.shared.global [%0], [%1], 16;\n" :: "r"(s), "l"(g));
}
#define LDSM4(v, addr) \
    asm volatile("ldmatrix.sync.aligned.m8n8.x4.shared.b16 {%0,%1,%2,%3}, [%4];" \
        : "=r"((v)[0]), "=r"((v)[1]), "=r"((v)[2]), "=r"((v)[3]) : "r"(addr))
#define MMA16816(d, a, b0, b1) \
    asm volatile("mma.sync.aligned.m16n8k16.row.col.f32.bf16.bf16.f32 " \
        "{%0,%1,%2,%3},{%4,%5,%6,%7},{%8,%9},{%0,%1,%2,%3};" \
        : "+f"((d)[0]), "+f"((d)[1]), "+f"((d)[2]), "+f"((d)[3]) \
        : "r"((a)[0]), "r"((a)[1]), "r"((a)[2]), "r"((a)[3]), "r"(b0), "r"(b1))

// ---------------- prep: weight bf16 cast + SSM params ----------------
__global__ void prep_kernel(const float* __restrict__ in_w, const float* __restrict__ out_w,
                            const float* __restrict__ A_log, const float* __restrict__ Bp,
                            const float* __restrict__ Cp, const float* __restrict__ log_dt){
    int stride = gridDim.x*blockDim.x;
    const int n1 = 2*DM*DM, n2 = DM*DM, n3 = DM*DS;
    for(int i = blockIdx.x*blockDim.x + threadIdx.x; i < n1+n2+n3; i += stride){
        if(i < n1){
            g_w1[i] = __float2bfloat16_rn(in_w[i]);
        } else if(i < n1+n2){
            g_w2[i-n1] = __float2bfloat16_rn(out_w[i-n1]);
        } else {
            int j = i - n1 - n2;
            int d = j >> 4;
            float dt = fminf(fmaxf(expf(log_dt[d]), 1e-4f), 1.0f);
            float Ab = expf(-expf(A_log[j]) * dt);
            Ab = fminf(fmaxf(Ab, 1e-8f), 1.0f - 1e-8f);
            g_Abar[j] = Ab;
            g_cbdt[j] = Cp[j] * Bp[j] * dt;
            float p = Ab;
            #pragma unroll
            for(int q = 0; q < 5; q++) p = p*p;   // Abar^32 (LC=32)
            g_Apow[j] = p;
        }
    }
}

// ---------------- layernorm (row = one block) ----------------
__global__ void ln_kernel(const float* __restrict__ x, const float* __restrict__ g,
                          const float* __restrict__ b){
    int r = blockIdx.x, t = threadIdx.x;
    float4 v = reinterpret_cast<const float4*>(x + (size_t)r*DM)[t];
    float s = v.x+v.y+v.z+v.w;
    float q = v.x*v.x + v.y*v.y + v.z*v.z + v.w*v.w;
    #pragma unroll
    for(int o = 16; o; o >>= 1){
        s += __shfl_xor_sync(0xffffffffu, s, o);
        q += __shfl_xor_sync(0xffffffffu, q, o);
    }
    __shared__ float ss[8], qs[8];
    int w = t >> 5, lane = t & 31;
    if(lane == 0){ ss[w] = s; qs[w] = q; }
    __syncthreads();
    s = 0.f; q = 0.f;
    #pragma unroll
    for(int i = 0; i < 8; i++){ s += ss[i]; q += qs[i]; }
    float mu  = s * (1.0f/DM);
    float var = q * (1.0f/DM) - mu*mu;
    float rs  = rsqrtf(var + 1e-5f);
    float4 gv = reinterpret_cast<const float4*>(g)[t];
    float4 bv = reinterpret_cast<const float4*>(b)[t];
    float o0 = (v.x-mu)*rs*gv.x + bv.x;
    float o1 = (v.y-mu)*rs*gv.y + bv.y;
    float o2 = (v.z-mu)*rs*gv.z + bv.z;
    float o3 = (v.w-mu)*rs*gv.w + bv.w;
    __nv_bfloat162 p0 = __floats2bfloat162_rn(o0, o1);
    __nv_bfloat162 p1 = __floats2bfloat162_rn(o2, o3);
    uint2 pk; pk.x = *(uint32_t*)&p0; pk.y = *(uint32_t*)&p1;
    reinterpret_cast<uint2*>(g_xn + (size_t)r*DM)[t] = pk;
}

// ---------------- HMMA GEMM: C[M,N] = A[M,K] @ B[N,K]^T + fused epilogue ------
// CTA tile 128(M) x 128(N), 8 warps (warp tile 32x64), K chunks of 32 bf16,
// 3-stage cp.async pipeline, ldmatrix.x4 fragments, XOR-swizzled smem.
// __launch_bounds__(256,2): 48KB smem + ~115 regs -> 2 CTAs/SM to fill
// the ~30% tensor-pipe idle seen at 1 CTA/SM.
// MODE 0: xz = xn @ in_w^T + in_b ; split + silu, bf16 out
// MODE 1: out = gated @ out_w^T + out_b + resid, clip, fp32 out
#define STG_BYTES 16384          // 8KB A + 8KB B
#define GEMM_SMEM (3*STG_BYTES + 128)

template<int MODE>
__global__ void __launch_bounds__(256, 2) gemm_hmma(const float* __restrict__ bias,
                                                    const float* __restrict__ resid,
                                                    float* __restrict__ outp){
    constexpr int K = DM, KB = K*2;
    const __nv_bfloat16* __restrict__ Am = (MODE==0) ? g_xn : g_gated;
    const __nv_bfloat16* __restrict__ Bm = (MODE==0) ? g_w1 : g_w2;

    extern __shared__ char smem_dyn[];
    uint32_t sbase = (uint32_t)__cvta_generic_to_shared(smem_dyn);
    sbase = (sbase + 127) & ~127u;

    int t = threadIdx.x, lane = t & 31, wid = t >> 5;
    int wm = wid >> 1, wn = wid & 1;             // 4 x 2 warps over 128x128
    int m0 = blockIdx.y * 128, n0 = blockIdx.x * 128;

    const char* gA = (const char*)Am + (size_t)m0 * KB;
    const char* gB = (const char*)Bm + (size_t)n0 * KB;

    auto load = [&](int k, int st){
        uint32_t sA = sbase + (uint32_t)st*STG_BYTES;
        uint32_t sB = sA + 8192;
        int koff = k*64;                          // bytes (32 bf16)
        #pragma unroll
        for(int i = 0; i < 2; i++){               // A: 128 rows x 4 x 16B
            int ci = t + i*256;
            int r = ci >> 2, c = ci & 3;
            cp16(sA + (uint32_t)(r*64 + ((c ^ ((r>>1)&3))<<4)),
                 gA + (size_t)r*KB + koff + c*16);
        }
        #pragma unroll
        for(int i = 0; i < 2; i++){               // B: 128 rows x 4 x 16B
            int ci = t + i*256;
            int r = ci >> 2, c = ci & 3;
            cp16(sB + (uint32_t)(r*64 + ((c ^ ((r>>1)&3))<<4)),
                 gB + (size_t)r*KB + koff + c*16);
        }
    };

    float acc[2][8][4];
    #pragma unroll
    for(int i=0;i<2;i++)
    #pragma unroll
    for(int j=0;j<8;j++)
    #pragma unroll
    for(int q=0;q<4;q++) acc[i][j][q] = 0.f;

    load(0, 0); asm volatile("cp.async.commit_group;");
    load(1, 1); asm volatile("cp.async.commit_group;");

    int la_r = lane & 15, la_k = lane >> 4;
    uint32_t sw = (uint32_t)((la_r >> 1) & 3);
    uint32_t aoff = (uint32_t)((wm*32 + la_r) * 64);
    uint32_t boff = (uint32_t)((wn*64 + la_r) * 64);

    #pragma unroll 1
    for(int k = 0; k < K/32; k++){                // 32 chunks
        int st = k % 3;
        asm volatile("cp.async.wait_group 1;");
        __syncthreads();
        uint32_t smA = sbase + (uint32_t)st*STG_BYTES + aoff;
        uint32_t smB = sbase + (uint32_t)st*STG_BYTES + 8192 + boff;
        #pragma unroll
        for(int ks = 0; ks < 2; ks++){            // 2 x k16
            uint32_t kx = (uint32_t)(((ks*2 + la_k) ^ sw) << 4);
            uint32_t a[2][4], b[4][4];
            #pragma unroll
            for(int mi = 0; mi < 2; mi++) LDSM4(a[mi], smA + mi*1024 + kx);
            #pragma unroll
            for(int ng = 0; ng < 4; ng++) LDSM4(b[ng], smB + ng*1024 + kx);
            #pragma unroll
            for(int mi = 0; mi < 2; mi++)
            #pragma unroll
            for(int ng = 0; ng < 4; ng++){
                MMA16816(acc[mi][2*ng],   a[mi], b[ng][0], b[ng][2]);
                MMA16816(acc[mi][2*ng+1], a[mi], b[ng][1], b[ng][3]);
            }
        }
        if(k + 2 < K/32) load(k + 2, (k + 2) % 3);
        asm volatile("cp.async.commit_group;");
    }

    // ---------------- epilogue (direct global stores) ----------------
    int grp = lane >> 2, c2 = (lane & 3) * 2;
    #pragma unroll
    for(int mi = 0; mi < 2; mi++){
        #pragma unroll
        for(int ni = 0; ni < 8; ni++){
            int row = m0 + wm*32 + mi*16 + grp;
            int col = n0 + wn*64 + ni*8 + c2;
            float b0 = __ldg(&bias[col]), b1 = __ldg(&bias[col+1]);
            #pragma unroll
            for(int h = 0; h < 2; h++){
                int rr = row + h*8;
                float v0 = acc[mi][ni][2*h+0] + b0;
                float v1 = acc[mi][ni][2*h+1] + b1;
                if(MODE == 0){
                    if(n0 >= DM){
                        v0 = v0 / (1.f + __expf(-v0));
                        v1 = v1 / (1.f + __expf(-v1));
                        __nv_bfloat162 p = __floats2bfloat162_rn(v0, v1);
                        *(uint32_t*)&g_zs[(size_t)rr*DM + col - DM] = *(uint32_t*)&p;
                    } else {
                        __nv_bfloat162 p = __floats2bfloat162_rn(v0, v1);
                        *(uint32_t*)&g_xproj[(size_t)rr*DM + col] = *(uint32_t*)&p;
                    }
                } else {
                    float2 rv = *(const float2*)&resid[(size_t)rr*DM + col];
                    v0 = fminf(fmaxf(v0 + rv.x, -10.f), 10.f);
                    v1 = fminf(fmaxf(v1 + rv.y, -10.f), 10.f);
                    float2 ov; ov.x = v0; ov.y = v1;
                    *(float2*)&outp[(size_t)rr*DM + col] = ov;
                }
            }
        }
    }
}

// ---------------- SSM chunked scan ----------------
__global__ void ssm_pass1(){
    int d = blockIdx.x*blockDim.x + threadIdx.x;
    int c = blockIdx.y, b = blockIdx.z;
    float Aa[DS];
    const float4* A4 = reinterpret_cast<const float4*>(g_Abar + d*DS);
    #pragma unroll
    for(int j=0;j<4;j++){ float4 v=A4[j]; Aa[4*j]=v.x; Aa[4*j+1]=v.y; Aa[4*j+2]=v.z; Aa[4*j+3]=v.w; }
    float s[DS];
    #pragma unroll
    for(int n=0;n<DS;n++) s[n] = 0.f;
    const __nv_bfloat16* u = g_xproj + (size_t)(b*LS + c*LC)*DM + d;
    #pragma unroll 4
    for(int tt = 0; tt < LC; ++tt){
        float uv = __bfloat162float(u[(size_t)tt*DM]);
        #pragma unroll
        for(int n=0;n<DS;n++) s[n] = fmaf(Aa[n], s[n], uv);
    }
    float4* F4 = reinterpret_cast<float4*>(g_F + (size_t)((c*NB + b)*DM + d)*DS);
    #pragma unroll
    for(int j=0;j<4;j++){ float4 v; v.x=s[4*j]; v.y=s[4*j+1]; v.z=s[4*j+2]; v.w=s[4*j+3]; F4[j]=v; }
}

__global__ void ssm_pass2(){
    int i = blockIdx.x*blockDim.x + threadIdx.x;      // over NB*DM*DS = 65536
    float Ap = g_Apow[i & (DM*DS - 1)];
    float s = 0.f;
    #pragma unroll 8
    for(int c = 0; c < NCH; c++){
        g_Sin[c*(NB*DM*DS) + i] = s;
        s = fmaf(Ap, s, g_F[c*(NB*DM*DS) + i]);
    }
}

__global__ void ssm_pass3(){
    int d = blockIdx.x*blockDim.x + threadIdx.x;
    int c = blockIdx.y, b = blockIdx.z;
    float Aa[DS], cb[DS], s[DS];
    const float4* A4 = reinterpret_cast<const float4*>(g_Abar + d*DS);
    const float4* C4 = reinterpret_cast<const float4*>(g_cbdt + d*DS);
    const float4* S4 = reinterpret_cast<const float4*>(g_Sin + (size_t)c*(NB*DM*DS) + (size_t)(b*DM + d)*DS);
    #pragma unroll
    for(int j=0;j<4;j++){
        float4 va=A4[j]; Aa[4*j]=va.x; Aa[4*j+1]=va.y; Aa[4*j+2]=va.z; Aa[4*j+3]=va.w;
        float4 vc=C4[j]; cb[4*j]=vc.x; cb[4*j+1]=vc.y; cb[4*j+2]=vc.z; cb[4*j+3]=vc.w;
        float4 vs=S4[j]; s[4*j]=vs.x;  s[4*j+1]=vs.y;  s[4*j+2]=vs.z;  s[4*j+3]=vs.w;
    }
    size_t base = (size_t)(b*LS + c*LC)*DM + d;
    const __nv_bfloat16* u  = g_xproj + base;
    const __nv_bfloat16* zp = g_zs    + base;
    __nv_bfloat16*       gp = g_gated + base;
    #pragma unroll 2
    for(int tt = 0; tt < LC; ++tt){
        float uv = __bfloat162float(u[(size_t)tt*DM]);
        #pragma unroll
        for(int n=0;n<DS;n++) s[n] = fmaf(Aa[n], s[n], uv);
        float y = 0.f;
        #pragma unroll
        for(int n=0;n<DS;n++) y = fmaf(cb[n], s[n], y);
        float zv = __bfloat162float(zp[(size_t)tt*DM]);
        gp[(size_t)tt*DM] = __float2bfloat16_rn(y * zv);
    }
}

// ---------------- launch ----------------
extern "C" void kernel_launch(void* const* d_in, const int* in_sizes, int n_in,
                              void* d_out, int out_size){
    const float* x      = (const float*)d_in[0];
    const float* A_log  = (const float*)d_in[1];
    const float* Bp     = (const float*)d_in[2];
    const float* Cp     = (const float*)d_in[3];
    const float* log_dt = (const float*)d_in[4];
    const float* in_w   = (const float*)d_in[5];
    const float* in_b   = (const float*)d_in[6];
    const float* out_w  = (const float*)d_in[7];
    const float* out_b  = (const float*)d_in[8];
    const float* ln_g   = (const float*)d_in[9];
    const float* ln_b   = (const float*)d_in[10];
    float* outp = (float*)d_out;

    cudaFuncSetAttribute(gemm_hmma<0>, cudaFuncAttributeMaxDynamicSharedMemorySize, GEMM_SMEM);
    cudaFuncSetAttribute(gemm_hmma<1>, cudaFuncAttributeMaxDynamicSharedMemorySize, GEMM_SMEM);

    prep_kernel<<<512, 256>>>(in_w, out_w, A_log, Bp, Cp, log_dt);
    ln_kernel<<<MR, 256>>>(x, ln_g, ln_b);
    gemm_hmma<0><<<dim3(2*DM/128, MR/128), 256, GEMM_SMEM>>>(in_b, nullptr, nullptr);
    ssm_pass1<<<dim3(DM/128, NCH, NB), 128>>>();
    ssm_pass2<<<(NB*DM*DS)/256, 256>>>();
    ssm_pass3<<<dim3(DM/128, NCH, NB), 128>>>();
    gemm_hmma<1><<<dim3(DM/128, MR/128), 256, GEMM_SMEM>>>(out_b, x, outp);
}

// round 11
// speedup vs baseline: 3.5960x; 1.0915x over previous
#include <cuda_runtime.h>
#include <cuda_bf16.h>
#include <cstdint>

#define DM 1024
#define DS 16
#define NB 4
#define LS 2048
#define MR (NB*LS)      // 8192 rows
#define LC 32           // scan chunk length
#define NCH (LS/LC)     // 64 chunks

// ---------------- scratch (device globals; no allocations) ----------------
__device__ __align__(256) __nv_bfloat16 g_xn[MR*DM];     // layernormed x (bf16)
__device__ __align__(256) __nv_bfloat16 g_w1[2*DM*DM];   // in_w bf16
__device__ __align__(256) __nv_bfloat16 g_w2[DM*DM];     // out_w bf16
__device__ __align__(256) __nv_bfloat16 g_xproj[MR*DM];  // ssm input u
__device__ __align__(256) __nv_bfloat16 g_zs[MR*DM];     // silu(z)
__device__ __align__(256) __nv_bfloat16 g_gated[MR*DM];  // y * silu(z)
__device__ __align__(256) float g_Abar[DM*DS];
__device__ __align__(256) float g_cbdt[DM*DS];
__device__ __align__(256) float g_Apow[DM*DS];           // Abar^LC
__device__ __align__(256) float g_F[NCH*NB*DM*DS];       // chunk-local end states
__device__ __align__(256) float g_Sin[NCH*NB*DM*DS];     // chunk incoming states

// ---------------- PTX helpers ----------------
__device__ __forceinline__ void cp16(uint32_t s, const void* g){
    asm volatile("cp.async.cg.shared.global [%0], [%1], 16;\n" :: "r"(s), "l"(g));
}
#define LDSM4(v, addr) \
    asm volatile("ldmatrix.sync.aligned.m8n8.x4.shared.b16 {%0,%1,%2,%3}, [%4];" \
        : "=r"((v)[0]), "=r"((v)[1]), "=r"((v)[2]), "=r"((v)[3]) : "r"(addr))
#define MMA16816(d, a, b0, b1) \
    asm volatile("mma.sync.aligned.m16n8k16.row.col.f32.bf16.bf16.f32 " \
        "{%0,%1,%2,%3},{%4,%5,%6,%7},{%8,%9},{%0,%1,%2,%3};" \
        : "+f"((d)[0]), "+f"((d)[1]), "+f"((d)[2]), "+f"((d)[3]) \
        : "r"((a)[0]), "r"((a)[1]), "r"((a)[2]), "r"((a)[3]), "r"(b0), "r"(b1))

// ---------------- prep: vectorized weight bf16 cast ----------------
__global__ void prep_w(const float* __restrict__ in_w, const float* __restrict__ out_w){
    const int n1 = 2*DM*DM/4, n2 = DM*DM/4;
    int stride = gridDim.x*blockDim.x;
    for(int i = blockIdx.x*blockDim.x + threadIdx.x; i < n1 + n2; i += stride){
        if(i < n1){
            float4 v = reinterpret_cast<const float4*>(in_w)[i];
            __nv_bfloat162 p0 = __floats2bfloat162_rn(v.x, v.y);
            __nv_bfloat162 p1 = __floats2bfloat162_rn(v.z, v.w);
            uint2 pk; pk.x = *(uint32_t*)&p0; pk.y = *(uint32_t*)&p1;
            reinterpret_cast<uint2*>(g_w1)[i] = pk;
        } else {
            int j = i - n1;
            float4 v = reinterpret_cast<const float4*>(out_w)[j];
            __nv_bfloat162 p0 = __floats2bfloat162_rn(v.x, v.y);
            __nv_bfloat162 p1 = __floats2bfloat162_rn(v.z, v.w);
            uint2 pk; pk.x = *(uint32_t*)&p0; pk.y = *(uint32_t*)&p1;
            reinterpret_cast<uint2*>(g_w2)[j] = pk;
        }
    }
}

// ---------------- prep: SSM params ----------------
__global__ void prep_ssm(const float* __restrict__ A_log, const float* __restrict__ Bp,
                         const float* __restrict__ Cp, const float* __restrict__ log_dt){
    int j = blockIdx.x*blockDim.x + threadIdx.x;   // over DM*DS
    int d = j >> 4;
    float dt = fminf(fmaxf(expf(log_dt[d]), 1e-4f), 1.0f);
    float Ab = expf(-expf(A_log[j]) * dt);
    Ab = fminf(fmaxf(Ab, 1e-8f), 1.0f - 1e-8f);
    g_Abar[j] = Ab;
    g_cbdt[j] = Cp[j] * Bp[j] * dt;
    float p = Ab;
    #pragma unroll
    for(int q = 0; q < 5; q++) p = p*p;            // Abar^32 (LC=32)
    g_Apow[j] = p;
}

// ---------------- layernorm (row = one block) ----------------
__global__ void ln_kernel(const float* __restrict__ x, const float* __restrict__ g,
                          const float* __restrict__ b){
    int r = blockIdx.x, t = threadIdx.x;
    float4 v = reinterpret_cast<const float4*>(x + (size_t)r*DM)[t];
    float s = v.x+v.y+v.z+v.w;
    float q = v.x*v.x + v.y*v.y + v.z*v.z + v.w*v.w;
    #pragma unroll
    for(int o = 16; o; o >>= 1){
        s += __shfl_xor_sync(0xffffffffu, s, o);
        q += __shfl_xor_sync(0xffffffffu, q, o);
    }
    __shared__ float ss[8], qs[8];
    int w = t >> 5, lane = t & 31;
    if(lane == 0){ ss[w] = s; qs[w] = q; }
    __syncthreads();
    s = 0.f; q = 0.f;
    #pragma unroll
    for(int i = 0; i < 8; i++){ s += ss[i]; q += qs[i]; }
    float mu  = s * (1.0f/DM);
    float var = q * (1.0f/DM) - mu*mu;
    float rs  = rsqrtf(var + 1e-5f);
    float4 gv = reinterpret_cast<const float4*>(g)[t];
    float4 bv = reinterpret_cast<const float4*>(b)[t];
    float o0 = (v.x-mu)*rs*gv.x + bv.x;
    float o1 = (v.y-mu)*rs*gv.y + bv.y;
    float o2 = (v.z-mu)*rs*gv.z + bv.z;
    float o3 = (v.w-mu)*rs*gv.w + bv.w;
    __nv_bfloat162 p0 = __floats2bfloat162_rn(o0, o1);
    __nv_bfloat162 p1 = __floats2bfloat162_rn(o2, o3);
    uint2 pk; pk.x = *(uint32_t*)&p0; pk.y = *(uint32_t*)&p1;
    reinterpret_cast<uint2*>(g_xn + (size_t)r*DM)[t] = pk;
}

// ---------------- HMMA GEMM (validated Round-7 version, unchanged) ----------
#define STG_BYTES 16384          // 8KB A + 8KB B
#define GEMM_SMEM (3*STG_BYTES + 128)

template<int MODE>
__global__ void __launch_bounds__(256, 2) gemm_hmma(const float* __restrict__ bias,
                                                    const float* __restrict__ resid,
                                                    float* __restrict__ outp){
    constexpr int K = DM, KB = K*2;
    const __nv_bfloat16* __restrict__ Am = (MODE==0) ? g_xn : g_gated;
    const __nv_bfloat16* __restrict__ Bm = (MODE==0) ? g_w1 : g_w2;

    extern __shared__ char smem_dyn[];
    uint32_t sbase = (uint32_t)__cvta_generic_to_shared(smem_dyn);
    sbase = (sbase + 127) & ~127u;

    int t = threadIdx.x, lane = t & 31, wid = t >> 5;
    int wm = wid >> 1, wn = wid & 1;             // 4 x 2 warps over 128x128
    int m0 = blockIdx.y * 128, n0 = blockIdx.x * 128;

    const char* gA = (const char*)Am + (size_t)m0 * KB;
    const char* gB = (const char*)Bm + (size_t)n0 * KB;

    auto load = [&](int k, int st){
        uint32_t sA = sbase + (uint32_t)st*STG_BYTES;
        uint32_t sB = sA + 8192;
        int koff = k*64;                          // bytes (32 bf16)
        #pragma unroll
        for(int i = 0; i < 2; i++){               // A: 128 rows x 4 x 16B
            int ci = t + i*256;
            int r = ci >> 2, c = ci & 3;
            cp16(sA + (uint32_t)(r*64 + ((c ^ ((r>>1)&3))<<4)),
                 gA + (size_t)r*KB + koff + c*16);
        }
        #pragma unroll
        for(int i = 0; i < 2; i++){               // B: 128 rows x 4 x 16B
            int ci = t + i*256;
            int r = ci >> 2, c = ci & 3;
            cp16(sB + (uint32_t)(r*64 + ((c ^ ((r>>1)&3))<<4)),
                 gB + (size_t)r*KB + koff + c*16);
        }
    };

    float acc[2][8][4];
    #pragma unroll
    for(int i=0;i<2;i++)
    #pragma unroll
    for(int j=0;j<8;j++)
    #pragma unroll
    for(int q=0;q<4;q++) acc[i][j][q] = 0.f;

    load(0, 0); asm volatile("cp.async.commit_group;");
    load(1, 1); asm volatile("cp.async.commit_group;");

    int la_r = lane & 15, la_k = lane >> 4;
    uint32_t sw = (uint32_t)((la_r >> 1) & 3);
    uint32_t aoff = (uint32_t)((wm*32 + la_r) * 64);
    uint32_t boff = (uint32_t)((wn*64 + la_r) * 64);

    #pragma unroll 1
    for(int k = 0; k < K/32; k++){                // 32 chunks
        int st = k % 3;
        asm volatile("cp.async.wait_group 1;");
        __syncthreads();
        uint32_t smA = sbase + (uint32_t)st*STG_BYTES + aoff;
        uint32_t smB = sbase + (uint32_t)st*STG_BYTES + 8192 + boff;
        #pragma unroll
        for(int ks = 0; ks < 2; ks++){            // 2 x k16
            uint32_t kx = (uint32_t)(((ks*2 + la_k) ^ sw) << 4);
            uint32_t a[2][4], b[4][4];
            #pragma unroll
            for(int mi = 0; mi < 2; mi++) LDSM4(a[mi], smA + mi*1024 + kx);
            #pragma unroll
            for(int ng = 0; ng < 4; ng++) LDSM4(b[ng], smB + ng*1024 + kx);
            #pragma unroll
            for(int mi = 0; mi < 2; mi++)
            #pragma unroll
            for(int ng = 0; ng < 4; ng++){
                MMA16816(acc[mi][2*ng],   a[mi], b[ng][0], b[ng][2]);
                MMA16816(acc[mi][2*ng+1], a[mi], b[ng][1], b[ng][3]);
            }
        }
        if(k + 2 < K/32) load(k + 2, (k + 2) % 3);
        asm volatile("cp.async.commit_group;");
    }

    int grp = lane >> 2, c2 = (lane & 3) * 2;
    #pragma unroll
    for(int mi = 0; mi < 2; mi++){
        #pragma unroll
        for(int ni = 0; ni < 8; ni++){
            int row = m0 + wm*32 + mi*16 + grp;
            int col = n0 + wn*64 + ni*8 + c2;
            float b0 = __ldg(&bias[col]), b1 = __ldg(&bias[col+1]);
            #pragma unroll
            for(int h = 0; h < 2; h++){
                int rr = row + h*8;
                float v0 = acc[mi][ni][2*h+0] + b0;
                float v1 = acc[mi][ni][2*h+1] + b1;
                if(MODE == 0){
                    if(n0 >= DM){
                        v0 = v0 / (1.f + __expf(-v0));
                        v1 = v1 / (1.f + __expf(-v1));
                        __nv_bfloat162 p = __floats2bfloat162_rn(v0, v1);
                        *(uint32_t*)&g_zs[(size_t)rr*DM + col - DM] = *(uint32_t*)&p;
                    } else {
                        __nv_bfloat162 p = __floats2bfloat162_rn(v0, v1);
                        *(uint32_t*)&g_xproj[(size_t)rr*DM + col] = *(uint32_t*)&p;
                    }
                } else {
                    float2 rv = *(const float2*)&resid[(size_t)rr*DM + col];
                    v0 = fminf(fmaxf(v0 + rv.x, -10.f), 10.f);
                    v1 = fminf(fmaxf(v1 + rv.y, -10.f), 10.f);
                    float2 ov; ov.x = v0; ov.y = v1;
                    *(float2*)&outp[(size_t)rr*DM + col] = ov;
                }
            }
        }
    }
}

// ---------------- SSM chunked scan (smem-staged tiles) ----------------
// Block = 128 threads = 128 channels; tile = LC(32) tokens x 128 channels.
// Coalesced 16B cp.async staging kills the strided-2B-load latency bound.
__global__ void ssm_pass1(){
    __shared__ __align__(16) __nv_bfloat16 su[LC*128];   // 8KB
    int t = threadIdx.x;
    int c = blockIdx.y, b = blockIdx.z;
    int d = blockIdx.x*128 + t;
    const char* gsrc = (const char*)(g_xproj + (size_t)(b*LS + c*LC)*DM + blockIdx.x*128);
    uint32_t sb = (uint32_t)__cvta_generic_to_shared(su);
    #pragma unroll
    for(int i = 0; i < 4; i++){                 // 512 x 16B chunks (32 rows x 256B)
        int idx = t + i*128;
        cp16(sb + (uint32_t)idx*16, gsrc + (size_t)(idx >> 4)*(DM*2) + (idx & 15)*16);
    }
    asm volatile("cp.async.commit_group;");
    float Aa[DS];
    const float4* A4 = reinterpret_cast<const float4*>(g_Abar + d*DS);
    #pragma unroll
    for(int j=0;j<4;j++){ float4 v=A4[j]; Aa[4*j]=v.x; Aa[4*j+1]=v.y; Aa[4*j+2]=v.z; Aa[4*j+3]=v.w; }
    float s[DS];
    #pragma unroll
    for(int n=0;n<DS;n++) s[n] = 0.f;
    asm volatile("cp.async.wait_group 0;");
    __syncthreads();
    #pragma unroll 8
    for(int tt = 0; tt < LC; ++tt){
        float uv = __bfloat162float(su[tt*128 + t]);
        #pragma unroll
        for(int n=0;n<DS;n++) s[n] = fmaf(Aa[n], s[n], uv);
    }
    float4* F4 = reinterpret_cast<float4*>(g_F + (size_t)((c*NB + b)*DM + d)*DS);
    #pragma unroll
    for(int j=0;j<4;j++){ float4 v; v.x=s[4*j]; v.y=s[4*j+1]; v.z=s[4*j+2]; v.w=s[4*j+3]; F4[j]=v; }
}

__global__ void ssm_pass2(){
    int i = blockIdx.x*blockDim.x + threadIdx.x;      // over NB*DM*DS = 65536
    float Ap = g_Apow[i & (DM*DS - 1)];
    float s = 0.f;
    #pragma unroll 8
    for(int c = 0; c < NCH; c++){
        g_Sin[c*(NB*DM*DS) + i] = s;
        s = fmaf(Ap, s, g_F[c*(NB*DM*DS) + i]);
    }
}

__global__ void ssm_pass3(){
    __shared__ __align__(16) __nv_bfloat16 su[LC*128];   // 8KB u
    __shared__ __align__(16) __nv_bfloat16 sz[LC*128];   // 8KB silu(z)
    __shared__ __align__(16) __nv_bfloat16 so[LC*128];   // 8KB out
    int t = threadIdx.x;
    int c = blockIdx.y, b = blockIdx.z;
    int d = blockIdx.x*128 + t;
    size_t goff = (size_t)(b*LS + c*LC)*DM + blockIdx.x*128;
    const char* gu = (const char*)(g_xproj + goff);
    const char* gz = (const char*)(g_zs + goff);
    uint32_t sbu = (uint32_t)__cvta_generic_to_shared(su);
    uint32_t sbz = (uint32_t)__cvta_generic_to_shared(sz);
    #pragma unroll
    for(int i = 0; i < 4; i++){
        int idx = t + i*128;
        size_t go = (size_t)(idx >> 4)*(DM*2) + (idx & 15)*16;
        cp16(sbu + (uint32_t)idx*16, gu + go);
        cp16(sbz + (uint32_t)idx*16, gz + go);
    }
    asm volatile("cp.async.commit_group;");

    float Aa[DS], cb[DS], s[DS];
    const float4* A4 = reinterpret_cast<const float4*>(g_Abar + d*DS);
    const float4* C4 = reinterpret_cast<const float4*>(g_cbdt + d*DS);
    const float4* S4 = reinterpret_cast<const float4*>(g_Sin + (size_t)c*(NB*DM*DS) + (size_t)(b*DM + d)*DS);
    #pragma unroll
    for(int j=0;j<4;j++){
        float4 va=A4[j]; Aa[4*j]=va.x; Aa[4*j+1]=va.y; Aa[4*j+2]=va.z; Aa[4*j+3]=va.w;
        float4 vc=C4[j]; cb[4*j]=vc.x; cb[4*j+1]=vc.y; cb[4*j+2]=vc.z; cb[4*j+3]=vc.w;
        float4 vs=S4[j]; s[4*j]=vs.x;  s[4*j+1]=vs.y;  s[4*j+2]=vs.z;  s[4*j+3]=vs.w;
    }
    asm volatile("cp.async.wait_group 0;");
    __syncthreads();
    #pragma unroll 4
    for(int tt = 0; tt < LC; ++tt){
        float uv = __bfloat162float(su[tt*128 + t]);
        #pragma unroll
        for(int n=0;n<DS;n++) s[n] = fmaf(Aa[n], s[n], uv);
        float y = 0.f;
        #pragma unroll
        for(int n=0;n<DS;n++) y = fmaf(cb[n], s[n], y);
        float zv = __bfloat162float(sz[tt*128 + t]);
        so[tt*128 + t] = __float2bfloat16_rn(y * zv);
    }
    __syncthreads();
    char* gg = (char*)(g_gated + goff);
    #pragma unroll
    for(int i = 0; i < 4; i++){                 // coalesced 16B stores
        int idx = t + i*128;
        *reinterpret_cast<uint4*>(gg + (size_t)(idx >> 4)*(DM*2) + (idx & 15)*16)
            = *reinterpret_cast<const uint4*>(reinterpret_cast<const char*>(so) + idx*16);
    }
}

// ---------------- launch ----------------
extern "C" void kernel_launch(void* const* d_in, const int* in_sizes, int n_in,
                              void* d_out, int out_size){
    const float* x      = (const float*)d_in[0];
    const float* A_log  = (const float*)d_in[1];
    const float* Bp     = (const float*)d_in[2];
    const float* Cp     = (const float*)d_in[3];
    const float* log_dt = (const float*)d_in[4];
    const float* in_w   = (const float*)d_in[5];
    const float* in_b   = (const float*)d_in[6];
    const float* out_w  = (const float*)d_in[7];
    const float* out_b  = (const float*)d_in[8];
    const float* ln_g   = (const float*)d_in[9];
    const float* ln_b   = (const float*)d_in[10];
    float* outp = (float*)d_out;

    cudaFuncSetAttribute(gemm_hmma<0>, cudaFuncAttributeMaxDynamicSharedMemorySize, GEMM_SMEM);
    cudaFuncSetAttribute(gemm_hmma<1>, cudaFuncAttributeMaxDynamicSharedMemorySize, GEMM_SMEM);

    prep_w<<<512, 256>>>(in_w, out_w);
    prep_ssm<<<(DM*DS)/256, 256>>>(A_log, Bp, Cp, log_dt);
    ln_kernel<<<MR, 256>>>(x, ln_g, ln_b);
    gemm_hmma<0><<<dim3(2*DM/128, MR/128), 256, GEMM_SMEM>>>(in_b, nullptr, nullptr);
    ssm_pass1<<<dim3(DM/128, NCH, NB), 128>>>();
    ssm_pass2<<<(NB*DM*DS)/256, 256>>>();
    ssm_pass3<<<dim3(DM/128, NCH, NB), 128>>>();
    gemm_hmma<1><<<dim3(DM/128, MR/128), 256, GEMM_SMEM>>>(out_b, x, outp);
}

// round 12
// speedup vs baseline: 3.6150x; 1.0053x over previous
#include <cuda_runtime.h>
#include <cuda_bf16.h>
#include <cstdint>

#define DM 1024
#define DS 16
#define NB 4
#define LS 2048
#define MR (NB*LS)      // 8192 rows
#define LC 32           // scan chunk length
#define NCH (LS/LC)     // 64 chunks

// ---------------- scratch (device globals; no allocations) ----------------
__device__ __align__(256) __nv_bfloat16 g_xn[MR*DM];     // layernormed x (bf16)
__device__ __align__(256) __nv_bfloat16 g_w1[2*DM*DM];   // in_w bf16
__device__ __align__(256) __nv_bfloat16 g_w2[DM*DM];     // out_w bf16
__device__ __align__(256) __nv_bfloat16 g_xproj[MR*DM];  // ssm input u
__device__ __align__(256) __nv_bfloat16 g_zs[MR*DM];     // silu(z)
__device__ __align__(256) __nv_bfloat16 g_gated[MR*DM];  // y * silu(z)
__device__ __align__(256) float g_Abar[DM*DS];
__device__ __align__(256) float g_cbdt[DM*DS];
__device__ __align__(256) float g_Apow[DM*DS];           // Abar^LC
__device__ __align__(256) float g_F[NCH*NB*DM*DS];       // chunk-local end states
__device__ __align__(256) float g_Sin[NCH*NB*DM*DS];     // chunk incoming states

// ---------------- PTX helpers ----------------
__device__ __forceinline__ void cp16(uint32_t s, const void* g){
    asm volatile("cp.async.cg.shared.global [%0], [%1], 16;\n" :: "r"(s), "l"(g));
}
#define LDSM4(v, addr) \
    asm volatile("ldmatrix.sync.aligned.m8n8.x4.shared.b16 {%0,%1,%2,%3}, [%4];" \
        : "=r"((v)[0]), "=r"((v)[1]), "=r"((v)[2]), "=r"((v)[3]) : "r"(addr))
#define MMA16816(d, a, b0, b1) \
    asm volatile("mma.sync.aligned.m16n8k16.row.col.f32.bf16.bf16.f32 " \
        "{%0,%1,%2,%3},{%4,%5,%6,%7},{%8,%9},{%0,%1,%2,%3};" \
        : "+f"((d)[0]), "+f"((d)[1]), "+f"((d)[2]), "+f"((d)[3]) \
        : "r"((a)[0]), "r"((a)[1]), "r"((a)[2]), "r"((a)[3]), "r"(b0), "r"(b1))

// ---------------- prep: weight bf16 cast (vectorized) + SSM params ----------
__global__ void prep_kernel(const float* __restrict__ in_w, const float* __restrict__ out_w,
                            const float* __restrict__ A_log, const float* __restrict__ Bp,
                            const float* __restrict__ Cp, const float* __restrict__ log_dt){
    const int n1 = 2*DM*DM/4, n2 = DM*DM/4, n3 = DM*DS;
    int stride = gridDim.x*blockDim.x;
    for(int i = blockIdx.x*blockDim.x + threadIdx.x; i < n1 + n2 + n3; i += stride){
        if(i < n1 + n2){
            const float* src = (i < n1) ? in_w : out_w;
            int j = (i < n1) ? i : i - n1;
            float4 v = reinterpret_cast<const float4*>(src)[j];
            __nv_bfloat162 p0 = __floats2bfloat162_rn(v.x, v.y);
            __nv_bfloat162 p1 = __floats2bfloat162_rn(v.z, v.w);
            uint2 pk; pk.x = *(uint32_t*)&p0; pk.y = *(uint32_t*)&p1;
            if(i < n1) reinterpret_cast<uint2*>(g_w1)[j] = pk;
            else       reinterpret_cast<uint2*>(g_w2)[j] = pk;
        } else {
            int j = i - n1 - n2;                  // over DM*DS
            int d = j >> 4;
            float dt = fminf(fmaxf(expf(log_dt[d]), 1e-4f), 1.0f);
            float Ab = expf(-expf(A_log[j]) * dt);
            Ab = fminf(fmaxf(Ab, 1e-8f), 1.0f - 1e-8f);
            g_Abar[j] = Ab;
            g_cbdt[j] = Cp[j] * Bp[j] * dt;
            float p = Ab;
            #pragma unroll
            for(int q = 0; q < 5; q++) p = p*p;   // Abar^32 (LC=32)
            g_Apow[j] = p;
        }
    }
}

// ---------------- layernorm (row = one block) ----------------
__global__ void ln_kernel(const float* __restrict__ x, const float* __restrict__ g,
                          const float* __restrict__ b){
    int r = blockIdx.x, t = threadIdx.x;
    float4 v = reinterpret_cast<const float4*>(x + (size_t)r*DM)[t];
    float s = v.x+v.y+v.z+v.w;
    float q = v.x*v.x + v.y*v.y + v.z*v.z + v.w*v.w;
    #pragma unroll
    for(int o = 16; o; o >>= 1){
        s += __shfl_xor_sync(0xffffffffu, s, o);
        q += __shfl_xor_sync(0xffffffffu, q, o);
    }
    __shared__ float ss[8], qs[8];
    int w = t >> 5, lane = t & 31;
    if(lane == 0){ ss[w] = s; qs[w] = q; }
    __syncthreads();
    s = 0.f; q = 0.f;
    #pragma unroll
    for(int i = 0; i < 8; i++){ s += ss[i]; q += qs[i]; }
    float mu  = s * (1.0f/DM);
    float var = q * (1.0f/DM) - mu*mu;
    float rs  = rsqrtf(var + 1e-5f);
    float4 gv = reinterpret_cast<const float4*>(g)[t];
    float4 bv = reinterpret_cast<const float4*>(b)[t];
    float o0 = (v.x-mu)*rs*gv.x + bv.x;
    float o1 = (v.y-mu)*rs*gv.y + bv.y;
    float o2 = (v.z-mu)*rs*gv.z + bv.z;
    float o3 = (v.w-mu)*rs*gv.w + bv.w;
    __nv_bfloat162 p0 = __floats2bfloat162_rn(o0, o1);
    __nv_bfloat162 p1 = __floats2bfloat162_rn(o2, o3);
    uint2 pk; pk.x = *(uint32_t*)&p0; pk.y = *(uint32_t*)&p1;
    reinterpret_cast<uint2*>(g_xn + (size_t)r*DM)[t] = pk;
}

// ---------------- HMMA GEMM: 128x128 tile, 4-stage pipeline, hoisted addrs ---
#define STG_BYTES 16384          // 8KB A + 8KB B per stage
#define NSTG 4
#define GEMM_SMEM (NSTG*STG_BYTES + 128)

template<int MODE>
__global__ void __launch_bounds__(256, 2) gemm_hmma(const float* __restrict__ bias,
                                                    const float* __restrict__ resid,
                                                    float* __restrict__ outp){
    constexpr int K = DM, KB = K*2;
    const __nv_bfloat16* __restrict__ Am = (MODE==0) ? g_xn : g_gated;
    const __nv_bfloat16* __restrict__ Bm = (MODE==0) ? g_w1 : g_w2;

    extern __shared__ char smem_dyn[];
    uint32_t sbase = (uint32_t)__cvta_generic_to_shared(smem_dyn);
    sbase = (sbase + 127) & ~127u;

    int t = threadIdx.x, lane = t & 31, wid = t >> 5;
    int wm = wid >> 1, wn = wid & 1;             // 4 x 2 warps over 128x128
    int m0 = blockIdx.y * 128, n0 = blockIdx.x * 128;

    // -------- hoisted load addressing: 2 A-chunks + 2 B-chunks per thread ----
    int r0 = t >> 2,        c0 = t & 3;
    int r1 = (t+256) >> 2,  c1 = (t+256) & 3;
    uint32_t soff0 = (uint32_t)(r0*64 + ((c0 ^ ((r0>>1)&3))<<4));
    uint32_t soff1 = (uint32_t)(r1*64 + ((c1 ^ ((r1>>1)&3))<<4));
    const char* pA0 = (const char*)Am + (size_t)(m0 + r0)*KB + c0*16;
    const char* pA1 = (const char*)Am + (size_t)(m0 + r1)*KB + c1*16;
    const char* pB0 = (const char*)Bm + (size_t)(n0 + r0)*KB + c0*16;
    const char* pB1 = (const char*)Bm + (size_t)(n0 + r1)*KB + c1*16;

    auto load = [&](uint32_t stg){
        cp16(stg + soff0,          pA0);
        cp16(stg + soff1,          pA1);
        cp16(stg + 8192 + soff0,   pB0);
        cp16(stg + 8192 + soff1,   pB1);
        pA0 += 64; pA1 += 64; pB0 += 64; pB1 += 64;
    };

    float acc[2][8][4];
    #pragma unroll
    for(int i=0;i<2;i++)
    #pragma unroll
    for(int j=0;j<8;j++)
    #pragma unroll
    for(int q=0;q<4;q++) acc[i][j][q] = 0.f;

    load(sbase + 0*STG_BYTES); asm volatile("cp.async.commit_group;");
    load(sbase + 1*STG_BYTES); asm volatile("cp.async.commit_group;");
    load(sbase + 2*STG_BYTES); asm volatile("cp.async.commit_group;");

    // -------- hoisted fragment addressing (loop-invariant swizzle cols) ------
    int la_r = lane & 15, la_k = lane >> 4;
    uint32_t sw  = (uint32_t)((la_r >> 1) & 3);
    uint32_t kx0 = ((uint32_t)(0*2 + la_k) ^ sw) << 4;
    uint32_t kx1 = ((uint32_t)(1*2 + la_k) ^ sw) << 4;
    uint32_t aoff = (uint32_t)((wm*32 + la_r) * 64);
    uint32_t boff = (uint32_t)((wn*64 + la_r) * 64) + 8192;

    #pragma unroll 1
    for(int k = 0; k < K/32; k++){                // 32 chunks
        uint32_t stg = sbase + (uint32_t)((k & 3) * STG_BYTES);
        asm volatile("cp.async.wait_group 2;");
        __syncthreads();
        if(k + 3 < K/32) load(sbase + (uint32_t)(((k+3) & 3) * STG_BYTES));
        asm volatile("cp.async.commit_group;");
        uint32_t smA = stg + aoff;
        uint32_t smB = stg + boff;
        #pragma unroll
        for(int ks = 0; ks < 2; ks++){            // 2 x k16
            uint32_t kx = ks ? kx1 : kx0;
            uint32_t a[2][4], b[4][4];
            #pragma unroll
            for(int mi = 0; mi < 2; mi++) LDSM4(a[mi], smA + mi*1024 + kx);
            #pragma unroll
            for(int ng = 0; ng < 4; ng++) LDSM4(b[ng], smB + ng*1024 + kx);
            #pragma unroll
            for(int mi = 0; mi < 2; mi++)
            #pragma unroll
            for(int ng = 0; ng < 4; ng++){
                MMA16816(acc[mi][2*ng],   a[mi], b[ng][0], b[ng][2]);
                MMA16816(acc[mi][2*ng+1], a[mi], b[ng][1], b[ng][3]);
            }
        }
    }

    int grp = lane >> 2, c2 = (lane & 3) * 2;
    #pragma unroll
    for(int mi = 0; mi < 2; mi++){
        #pragma unroll
        for(int ni = 0; ni < 8; ni++){
            int row = m0 + wm*32 + mi*16 + grp;
            int col = n0 + wn*64 + ni*8 + c2;
            float b0 = __ldg(&bias[col]), b1 = __ldg(&bias[col+1]);
            #pragma unroll
            for(int h = 0; h < 2; h++){
                int rr = row + h*8;
                float v0 = acc[mi][ni][2*h+0] + b0;
                float v1 = acc[mi][ni][2*h+1] + b1;
                if(MODE == 0){
                    if(n0 >= DM){
                        v0 = v0 / (1.f + __expf(-v0));
                        v1 = v1 / (1.f + __expf(-v1));
                        __nv_bfloat162 p = __floats2bfloat162_rn(v0, v1);
                        *(uint32_t*)&g_zs[(size_t)rr*DM + col - DM] = *(uint32_t*)&p;
                    } else {
                        __nv_bfloat162 p = __floats2bfloat162_rn(v0, v1);
                        *(uint32_t*)&g_xproj[(size_t)rr*DM + col] = *(uint32_t*)&p;
                    }
                } else {
                    float2 rv = *(const float2*)&resid[(size_t)rr*DM + col];
                    v0 = fminf(fmaxf(v0 + rv.x, -10.f), 10.f);
                    v1 = fminf(fmaxf(v1 + rv.y, -10.f), 10.f);
                    float2 ov; ov.x = v0; ov.y = v1;
                    *(float2*)&outp[(size_t)rr*DM + col] = ov;
                }
            }
        }
    }
}

// ---------------- SSM chunked scan (smem-staged tiles, validated) ------------
__global__ void ssm_pass1(){
    __shared__ __align__(16) __nv_bfloat16 su[LC*128];   // 8KB
    int t = threadIdx.x;
    int c = blockIdx.y, b = blockIdx.z;
    int d = blockIdx.x*128 + t;
    const char* gsrc = (const char*)(g_xproj + (size_t)(b*LS + c*LC)*DM + blockIdx.x*128);
    uint32_t sb = (uint32_t)__cvta_generic_to_shared(su);
    #pragma unroll
    for(int i = 0; i < 4; i++){                 // 512 x 16B chunks (32 rows x 256B)
        int idx = t + i*128;
        cp16(sb + (uint32_t)idx*16, gsrc + (size_t)(idx >> 4)*(DM*2) + (idx & 15)*16);
    }
    asm volatile("cp.async.commit_group;");
    float Aa[DS];
    const float4* A4 = reinterpret_cast<const float4*>(g_Abar + d*DS);
    #pragma unroll
    for(int j=0;j<4;j++){ float4 v=A4[j]; Aa[4*j]=v.x; Aa[4*j+1]=v.y; Aa[4*j+2]=v.z; Aa[4*j+3]=v.w; }
    float s[DS];
    #pragma unroll
    for(int n=0;n<DS;n++) s[n] = 0.f;
    asm volatile("cp.async.wait_group 0;");
    __syncthreads();
    #pragma unroll 8
    for(int tt = 0; tt < LC; ++tt){
        float uv = __bfloat162float(su[tt*128 + t]);
        #pragma unroll
        for(int n=0;n<DS;n++) s[n] = fmaf(Aa[n], s[n], uv);
    }
    float4* F4 = reinterpret_cast<float4*>(g_F + (size_t)((c*NB + b)*DM + d)*DS);
    #pragma unroll
    for(int j=0;j<4;j++){ float4 v; v.x=s[4*j]; v.y=s[4*j+1]; v.z=s[4*j+2]; v.w=s[4*j+3]; F4[j]=v; }
}

__global__ void ssm_pass2(){
    int i = blockIdx.x*blockDim.x + threadIdx.x;      // over NB*DM*DS = 65536
    float Ap = g_Apow[i & (DM*DS - 1)];
    float s = 0.f;
    #pragma unroll 8
    for(int c = 0; c < NCH; c++){
        g_Sin[c*(NB*DM*DS) + i] = s;
        s = fmaf(Ap, s, g_F[c*(NB*DM*DS) + i]);
    }
}

__global__ void ssm_pass3(){
    __shared__ __align__(16) __nv_bfloat16 su[LC*128];   // 8KB u
    __shared__ __align__(16) __nv_bfloat16 sz[LC*128];   // 8KB silu(z)
    __shared__ __align__(16) __nv_bfloat16 so[LC*128];   // 8KB out
    int t = threadIdx.x;
    int c = blockIdx.y, b = blockIdx.z;
    int d = blockIdx.x*128 + t;
    size_t goff = (size_t)(b*LS + c*LC)*DM + blockIdx.x*128;
    const char* gu = (const char*)(g_xproj + goff);
    const char* gz = (const char*)(g_zs + goff);
    uint32_t sbu = (uint32_t)__cvta_generic_to_shared(su);
    uint32_t sbz = (uint32_t)__cvta_generic_to_shared(sz);
    #pragma unroll
    for(int i = 0; i < 4; i++){
        int idx = t + i*128;
        size_t go = (size_t)(idx >> 4)*(DM*2) + (idx & 15)*16;
        cp16(sbu + (uint32_t)idx*16, gu + go);
        cp16(sbz + (uint32_t)idx*16, gz + go);
    }
    asm volatile("cp.async.commit_group;");

    float Aa[DS], cb[DS], s[DS];
    const float4* A4 = reinterpret_cast<const float4*>(g_Abar + d*DS);
    const float4* C4 = reinterpret_cast<const float4*>(g_cbdt + d*DS);
    const float4* S4 = reinterpret_cast<const float4*>(g_Sin + (size_t)c*(NB*DM*DS) + (size_t)(b*DM + d)*DS);
    #pragma unroll
    for(int j=0;j<4;j++){
        float4 va=A4[j]; Aa[4*j]=va.x; Aa[4*j+1]=va.y; Aa[4*j+2]=va.z; Aa[4*j+3]=va.w;
        float4 vc=C4[j]; cb[4*j]=vc.x; cb[4*j+1]=vc.y; cb[4*j+2]=vc.z; cb[4*j+3]=vc.w;
        float4 vs=S4[j]; s[4*j]=vs.x;  s[4*j+1]=vs.y;  s[4*j+2]=vs.z;  s[4*j+3]=vs.w;
    }
    asm volatile("cp.async.wait_group 0;");
    __syncthreads();
    #pragma unroll 4
    for(int tt = 0; tt < LC; ++tt){
        float uv = __bfloat162float(su[tt*128 + t]);
        #pragma unroll
        for(int n=0;n<DS;n++) s[n] = fmaf(Aa[n], s[n], uv);
        float y = 0.f;
        #pragma unroll
        for(int n=0;n<DS;n++) y = fmaf(cb[n], s[n], y);
        float zv = __bfloat162float(sz[tt*128 + t]);
        so[tt*128 + t] = __float2bfloat16_rn(y * zv);
    }
    __syncthreads();
    char* gg = (char*)(g_gated + goff);
    #pragma unroll
    for(int i = 0; i < 4; i++){                 // coalesced 16B stores
        int idx = t + i*128;
        *reinterpret_cast<uint4*>(gg + (size_t)(idx >> 4)*(DM*2) + (idx & 15)*16)
            = *reinterpret_cast<const uint4*>(reinterpret_cast<const char*>(so) + idx*16);
    }
}

// ---------------- launch ----------------
extern "C" void kernel_launch(void* const* d_in, const int* in_sizes, int n_in,
                              void* d_out, int out_size){
    const float* x      = (const float*)d_in[0];
    const float* A_log  = (const float*)d_in[1];
    const float* Bp     = (const float*)d_in[2];
    const float* Cp     = (const float*)d_in[3];
    const float* log_dt = (const float*)d_in[4];
    const float* in_w   = (const float*)d_in[5];
    const float* in_b   = (const float*)d_in[6];
    const float* out_w  = (const float*)d_in[7];
    const float* out_b  = (const float*)d_in[8];
    const float* ln_g   = (const float*)d_in[9];
    const float* ln_b   = (const float*)d_in[10];
    float* outp = (float*)d_out;

    cudaFuncSetAttribute(gemm_hmma<0>, cudaFuncAttributeMaxDynamicSharedMemorySize, GEMM_SMEM);
    cudaFuncSetAttribute(gemm_hmma<1>, cudaFuncAttributeMaxDynamicSharedMemorySize, GEMM_SMEM);

    prep_kernel<<<512, 256>>>(in_w, out_w, A_log, Bp, Cp, log_dt);
    ln_kernel<<<MR, 256>>>(x, ln_g, ln_b);
    gemm_hmma<0><<<dim3(2*DM/128, MR/128), 256, GEMM_SMEM>>>(in_b, nullptr, nullptr);
    ssm_pass1<<<dim3(DM/128, NCH, NB), 128>>>();
    ssm_pass2<<<(NB*DM*DS)/256, 256>>>();
    ssm_pass3<<<dim3(DM/128, NCH, NB), 128>>>();
    gemm_hmma<1><<<dim3(DM/128, MR/128), 256, GEMM_SMEM>>>(out_b, x, outp);
}

// round 13
// speedup vs baseline: 3.8252x; 1.0582x over previous
#include <cuda_runtime.h>
#include <cuda_bf16.h>
#include <cstdint>

#define DM 1024
#define DS 16
#define NB 4
#define LS 2048
#define MR (NB*LS)      // 8192 rows
#define LC 32           // scan chunk length
#define NCH (LS/LC)     // 64 chunks

// ---------------- scratch (device globals; no allocations) ----------------
__device__ __align__(256) __nv_bfloat16 g_xn[MR*DM];     // layernormed x (bf16)
__device__ __align__(256) __nv_bfloat16 g_w1[2*DM*DM];   // in_w bf16
__device__ __align__(256) __nv_bfloat16 g_w2[DM*DM];     // out_w bf16
__device__ __align__(256) __nv_bfloat16 g_xproj[MR*DM];  // ssm input u
__device__ __align__(256) __nv_bfloat16 g_zs[MR*DM];     // silu(z)
__device__ __align__(256) __nv_bfloat16 g_gated[MR*DM];  // y * silu(z)
__device__ __align__(256) float g_Abar[DM*DS];
__device__ __align__(256) float g_cbdt[DM*DS];
__device__ __align__(256) float g_Apow[DM*DS];           // Abar^LC
__device__ __align__(256) float g_F[NCH*NB*DM*DS];       // chunk-local end states
__device__ __align__(256) float g_Sin[NCH*NB*DM*DS];     // chunk incoming states

// ---------------- PTX helpers ----------------
__device__ __forceinline__ void cp16(uint32_t s, const void* g){
    asm volatile("cp.async.cg.shared.global [%0], [%1], 16;\n" :: "r"(s), "l"(g));
}
#define LDSM4(v, addr) \
    asm volatile("ldmatrix.sync.aligned.m8n8.x4.shared.b16 {%0,%1,%2,%3}, [%4];" \
        : "=r"((v)[0]), "=r"((v)[1]), "=r"((v)[2]), "=r"((v)[3]) : "r"(addr))
#define MMA16816(d, a, b0, b1) \
    asm volatile("mma.sync.aligned.m16n8k16.row.col.f32.bf16.bf16.f32 " \
        "{%0,%1,%2,%3},{%4,%5,%6,%7},{%8,%9},{%0,%1,%2,%3};" \
        : "+f"((d)[0]), "+f"((d)[1]), "+f"((d)[2]), "+f"((d)[3]) \
        : "r"((a)[0]), "r"((a)[1]), "r"((a)[2]), "r"((a)[3]), "r"(b0), "r"(b1))

// ---------------- prep: weight bf16 cast (vectorized) + SSM params ----------
__global__ void prep_kernel(const float* __restrict__ in_w, const float* __restrict__ out_w,
                            const float* __restrict__ A_log, const float* __restrict__ Bp,
                            const float* __restrict__ Cp, const float* __restrict__ log_dt){
    const int n1 = 2*DM*DM/4, n2 = DM*DM/4, n3 = DM*DS;
    int stride = gridDim.x*blockDim.x;
    for(int i = blockIdx.x*blockDim.x + threadIdx.x; i < n1 + n2 + n3; i += stride){
        if(i < n1 + n2){
            const float* src = (i < n1) ? in_w : out_w;
            int j = (i < n1) ? i : i - n1;
            float4 v = reinterpret_cast<const float4*>(src)[j];
            __nv_bfloat162 p0 = __floats2bfloat162_rn(v.x, v.y);
            __nv_bfloat162 p1 = __floats2bfloat162_rn(v.z, v.w);
            uint2 pk; pk.x = *(uint32_t*)&p0; pk.y = *(uint32_t*)&p1;
            if(i < n1) reinterpret_cast<uint2*>(g_w1)[j] = pk;
            else       reinterpret_cast<uint2*>(g_w2)[j] = pk;
        } else {
            int j = i - n1 - n2;                  // over DM*DS
            int d = j >> 4;
            float dt = fminf(fmaxf(expf(log_dt[d]), 1e-4f), 1.0f);
            float Ab = expf(-expf(A_log[j]) * dt);
            Ab = fminf(fmaxf(Ab, 1e-8f), 1.0f - 1e-8f);
            g_Abar[j] = Ab;
            g_cbdt[j] = Cp[j] * Bp[j] * dt;
            float p = Ab;
            #pragma unroll
            for(int q = 0; q < 5; q++) p = p*p;   // Abar^32 (LC=32)
            g_Apow[j] = p;
        }
    }
}

// ---------------- layernorm (row = one block) ----------------
__global__ void ln_kernel(const float* __restrict__ x, const float* __restrict__ g,
                          const float* __restrict__ b){
    int r = blockIdx.x, t = threadIdx.x;
    float4 v = reinterpret_cast<const float4*>(x + (size_t)r*DM)[t];
    float s = v.x+v.y+v.z+v.w;
    float q = v.x*v.x + v.y*v.y + v.z*v.z + v.w*v.w;
    #pragma unroll
    for(int o = 16; o; o >>= 1){
        s += __shfl_xor_sync(0xffffffffu, s, o);
        q += __shfl_xor_sync(0xffffffffu, q, o);
    }
    __shared__ float ss[8], qs[8];
    int w = t >> 5, lane = t & 31;
    if(lane == 0){ ss[w] = s; qs[w] = q; }
    __syncthreads();
    s = 0.f; q = 0.f;
    #pragma unroll
    for(int i = 0; i < 8; i++){ s += ss[i]; q += qs[i]; }
    float mu  = s * (1.0f/DM);
    float var = q * (1.0f/DM) - mu*mu;
    float rs  = rsqrtf(var + 1e-5f);
    float4 gv = reinterpret_cast<const float4*>(g)[t];
    float4 bv = reinterpret_cast<const float4*>(b)[t];
    float o0 = (v.x-mu)*rs*gv.x + bv.x;
    float o1 = (v.y-mu)*rs*gv.y + bv.y;
    float o2 = (v.z-mu)*rs*gv.z + bv.z;
    float o3 = (v.w-mu)*rs*gv.w + bv.w;
    __nv_bfloat162 p0 = __floats2bfloat162_rn(o0, o1);
    __nv_bfloat162 p1 = __floats2bfloat162_rn(o2, o3);
    uint2 pk; pk.x = *(uint32_t*)&p0; pk.y = *(uint32_t*)&p1;
    reinterpret_cast<uint2*>(g_xn + (size_t)r*DM)[t] = pk;
}

// ---------------- HMMA GEMM: 128x128 tile, K=64 stages, 3-stage pipeline -----
// 16 barriers per CTA (vs 32): 4 independent k16 groups between syncs.
// Stage = 16KB A + 16KB B (128B row pitch, 8-way XOR swizzle c^(r&7)).
#define STG_BYTES 32768
#define NSTG 3
#define GEMM_SMEM (NSTG*STG_BYTES + 128)

template<int MODE>
__global__ void __launch_bounds__(256, 2) gemm_hmma(const float* __restrict__ bias,
                                                    const float* __restrict__ resid,
                                                    float* __restrict__ outp){
    constexpr int K = DM, KB = K*2;
    const __nv_bfloat16* __restrict__ Am = (MODE==0) ? g_xn : g_gated;
    const __nv_bfloat16* __restrict__ Bm = (MODE==0) ? g_w1 : g_w2;

    extern __shared__ char smem_dyn[];
    uint32_t sbase = (uint32_t)__cvta_generic_to_shared(smem_dyn);
    sbase = (sbase + 127) & ~127u;

    int t = threadIdx.x, lane = t & 31, wid = t >> 5;
    int wm = wid >> 1, wn = wid & 1;             // 4 x 2 warps over 128x128
    int m0 = blockIdx.y * 128, n0 = blockIdx.x * 128;

    // -------- hoisted load addressing: 4 A-chunks + 4 B-chunks per thread ----
    // Per stage: A 128 rows x 8 x 16B (1024 chunks), B same. 256 threads.
    uint32_t soff[4];
    const char* pA[4];
    const char* pB[4];
    #pragma unroll
    for(int i = 0; i < 4; i++){
        int idx = t + i*256;
        int r = idx >> 3, c = idx & 7;
        soff[i] = (uint32_t)(r*128 + ((c ^ (r & 7)) << 4));
        pA[i] = (const char*)Am + (size_t)(m0 + r)*KB + c*16;
        pB[i] = (const char*)Bm + (size_t)(n0 + r)*KB + c*16;
    }

    auto load = [&](uint32_t stg){
        #pragma unroll
        for(int i = 0; i < 4; i++){
            cp16(stg + soff[i],          pA[i]);
            cp16(stg + 16384 + soff[i],  pB[i]);
            pA[i] += 128; pB[i] += 128;
        }
    };

    float acc[2][8][4];
    #pragma unroll
    for(int i=0;i<2;i++)
    #pragma unroll
    for(int j=0;j<8;j++)
    #pragma unroll
    for(int q=0;q<4;q++) acc[i][j][q] = 0.f;

    load(sbase + 0*STG_BYTES); asm volatile("cp.async.commit_group;");
    load(sbase + 1*STG_BYTES); asm volatile("cp.async.commit_group;");

    // -------- hoisted fragment addressing ------------------------------------
    int la_r = lane & 15, la_k = lane >> 4;
    uint32_t sw  = (uint32_t)(la_r & 7);
    uint32_t kx[4];
    #pragma unroll
    for(int kg = 0; kg < 4; kg++)
        kx[kg] = (((uint32_t)(kg*2 + la_k)) ^ sw) << 4;
    uint32_t aoff = (uint32_t)((wm*32 + la_r) * 128);
    uint32_t boff = (uint32_t)((wn*64 + la_r) * 128) + 16384;

    const int NCHK = K/64;                        // 16 chunks
    #pragma unroll 1
    for(int k = 0; k < NCHK; k++){
        uint32_t stg = sbase + (uint32_t)((k % 3) * STG_BYTES);
        asm volatile("cp.async.wait_group 1;");
        __syncthreads();
        if(k + 2 < NCHK) load(sbase + (uint32_t)(((k+2) % 3) * STG_BYTES));
        asm volatile("cp.async.commit_group;");
        uint32_t smA = stg + aoff;
        uint32_t smB = stg + boff;
        #pragma unroll
        for(int kg = 0; kg < 4; kg++){            // 4 x k16 between barriers
            uint32_t kc = kx[kg];
            uint32_t a[2][4], b[4][4];
            #pragma unroll
            for(int mi = 0; mi < 2; mi++) LDSM4(a[mi], smA + mi*2048 + kc);
            #pragma unroll
            for(int ng = 0; ng < 4; ng++) LDSM4(b[ng], smB + ng*2048 + kc);
            #pragma unroll
            for(int mi = 0; mi < 2; mi++)
            #pragma unroll
            for(int ng = 0; ng < 4; ng++){
                MMA16816(acc[mi][2*ng],   a[mi], b[ng][0], b[ng][2]);
                MMA16816(acc[mi][2*ng+1], a[mi], b[ng][1], b[ng][3]);
            }
        }
    }

    int grp = lane >> 2, c2 = (lane & 3) * 2;
    #pragma unroll
    for(int mi = 0; mi < 2; mi++){
        #pragma unroll
        for(int ni = 0; ni < 8; ni++){
            int row = m0 + wm*32 + mi*16 + grp;
            int col = n0 + wn*64 + ni*8 + c2;
            float b0 = __ldg(&bias[col]), b1 = __ldg(&bias[col+1]);
            #pragma unroll
            for(int h = 0; h < 2; h++){
                int rr = row + h*8;
                float v0 = acc[mi][ni][2*h+0] + b0;
                float v1 = acc[mi][ni][2*h+1] + b1;
                if(MODE == 0){
                    if(n0 >= DM){
                        v0 = v0 / (1.f + __expf(-v0));
                        v1 = v1 / (1.f + __expf(-v1));
                        __nv_bfloat162 p = __floats2bfloat162_rn(v0, v1);
                        *(uint32_t*)&g_zs[(size_t)rr*DM + col - DM] = *(uint32_t*)&p;
                    } else {
                        __nv_bfloat162 p = __floats2bfloat162_rn(v0, v1);
                        *(uint32_t*)&g_xproj[(size_t)rr*DM + col] = *(uint32_t*)&p;
                    }
                } else {
                    float2 rv = *(const float2*)&resid[(size_t)rr*DM + col];
                    v0 = fminf(fmaxf(v0 + rv.x, -10.f), 10.f);
                    v1 = fminf(fmaxf(v1 + rv.y, -10.f), 10.f);
                    float2 ov; ov.x = v0; ov.y = v1;
                    *(float2*)&outp[(size_t)rr*DM + col] = ov;
                }
            }
        }
    }
}

// ---------------- SSM chunked scan (smem-staged tiles, validated) ------------
__global__ void ssm_pass1(){
    __shared__ __align__(16) __nv_bfloat16 su[LC*128];   // 8KB
    int t = threadIdx.x;
    int c = blockIdx.y, b = blockIdx.z;
    int d = blockIdx.x*128 + t;
    const char* gsrc = (const char*)(g_xproj + (size_t)(b*LS + c*LC)*DM + blockIdx.x*128);
    uint32_t sb = (uint32_t)__cvta_generic_to_shared(su);
    #pragma unroll
    for(int i = 0; i < 4; i++){                 // 512 x 16B chunks (32 rows x 256B)
        int idx = t + i*128;
        cp16(sb + (uint32_t)idx*16, gsrc + (size_t)(idx >> 4)*(DM*2) + (idx & 15)*16);
    }
    asm volatile("cp.async.commit_group;");
    float Aa[DS];
    const float4* A4 = reinterpret_cast<const float4*>(g_Abar + d*DS);
    #pragma unroll
    for(int j=0;j<4;j++){ float4 v=A4[j]; Aa[4*j]=v.x; Aa[4*j+1]=v.y; Aa[4*j+2]=v.z; Aa[4*j+3]=v.w; }
    float s[DS];
    #pragma unroll
    for(int n=0;n<DS;n++) s[n] = 0.f;
    asm volatile("cp.async.wait_group 0;");
    __syncthreads();
    #pragma unroll 8
    for(int tt = 0; tt < LC; ++tt){
        float uv = __bfloat162float(su[tt*128 + t]);
        #pragma unroll
        for(int n=0;n<DS;n++) s[n] = fmaf(Aa[n], s[n], uv);
    }
    float4* F4 = reinterpret_cast<float4*>(g_F + (size_t)((c*NB + b)*DM + d)*DS);
    #pragma unroll
    for(int j=0;j<4;j++){ float4 v; v.x=s[4*j]; v.y=s[4*j+1]; v.z=s[4*j+2]; v.w=s[4*j+3]; F4[j]=v; }
}

__global__ void ssm_pass2(){
    int i = blockIdx.x*blockDim.x + threadIdx.x;      // over NB*DM*DS = 65536
    float Ap = g_Apow[i & (DM*DS - 1)];
    float s = 0.f;
    #pragma unroll 8
    for(int c = 0; c < NCH; c++){
        g_Sin[c*(NB*DM*DS) + i] = s;
        s = fmaf(Ap, s, g_F[c*(NB*DM*DS) + i]);
    }
}

__global__ void ssm_pass3(){
    __shared__ __align__(16) __nv_bfloat16 su[LC*128];   // 8KB u
    __shared__ __align__(16) __nv_bfloat16 sz[LC*128];   // 8KB silu(z)
    __shared__ __align__(16) __nv_bfloat16 so[LC*128];   // 8KB out
    int t = threadIdx.x;
    int c = blockIdx.y, b = blockIdx.z;
    int d = blockIdx.x*128 + t;
    size_t goff = (size_t)(b*LS + c*LC)*DM + blockIdx.x*128;
    const char* gu = (const char*)(g_xproj + goff);
    const char* gz = (const char*)(g_zs + goff);
    uint32_t sbu = (uint32_t)__cvta_generic_to_shared(su);
    uint32_t sbz = (uint32_t)__cvta_generic_to_shared(sz);
    #pragma unroll
    for(int i = 0; i < 4; i++){
        int idx = t + i*128;
        size_t go = (size_t)(idx >> 4)*(DM*2) + (idx & 15)*16;
        cp16(sbu + (uint32_t)idx*16, gu + go);
        cp16(sbz + (uint32_t)idx*16, gz + go);
    }
    asm volatile("cp.async.commit_group;");

    float Aa[DS], cb[DS], s[DS];
    const float4* A4 = reinterpret_cast<const float4*>(g_Abar + d*DS);
    const float4* C4 = reinterpret_cast<const float4*>(g_cbdt + d*DS);
    const float4* S4 = reinterpret_cast<const float4*>(g_Sin + (size_t)c*(NB*DM*DS) + (size_t)(b*DM + d)*DS);
    #pragma unroll
    for(int j=0;j<4;j++){
        float4 va=A4[j]; Aa[4*j]=va.x; Aa[4*j+1]=va.y; Aa[4*j+2]=va.z; Aa[4*j+3]=va.w;
        float4 vc=C4[j]; cb[4*j]=vc.x; cb[4*j+1]=vc.y; cb[4*j+2]=vc.z; cb[4*j+3]=vc.w;
        float4 vs=S4[j]; s[4*j]=vs.x;  s[4*j+1]=vs.y;  s[4*j+2]=vs.z;  s[4*j+3]=vs.w;
    }
    asm volatile("cp.async.wait_group 0;");
    __syncthreads();
    #pragma unroll 4
    for(int tt = 0; tt < LC; ++tt){
        float uv = __bfloat162float(su[tt*128 + t]);
        #pragma unroll
        for(int n=0;n<DS;n++) s[n] = fmaf(Aa[n], s[n], uv);
        float y = 0.f;
        #pragma unroll
        for(int n=0;n<DS;n++) y = fmaf(cb[n], s[n], y);
        float zv = __bfloat162float(sz[tt*128 + t]);
        so[tt*128 + t] = __float2bfloat16_rn(y * zv);
    }
    __syncthreads();
    char* gg = (char*)(g_gated + goff);
    #pragma unroll
    for(int i = 0; i < 4; i++){                 // coalesced 16B stores
        int idx = t + i*128;
        *reinterpret_cast<uint4*>(gg + (size_t)(idx >> 4)*(DM*2) + (idx & 15)*16)
            = *reinterpret_cast<const uint4*>(reinterpret_cast<const char*>(so) + idx*16);
    }
}

// ---------------- launch ----------------
extern "C" void kernel_launch(void* const* d_in, const int* in_sizes, int n_in,
                              void* d_out, int out_size){
    const float* x      = (const float*)d_in[0];
    const float* A_log  = (const float*)d_in[1];
    const float* Bp     = (const float*)d_in[2];
    const float* Cp     = (const float*)d_in[3];
    const float* log_dt = (const float*)d_in[4];
    const float* in_w   = (const float*)d_in[5];
    const float* in_b   = (const float*)d_in[6];
    const float* out_w  = (const float*)d_in[7];
    const float* out_b  = (const float*)d_in[8];
    const float* ln_g   = (const float*)d_in[9];
    const float* ln_b   = (const float*)d_in[10];
    float* outp = (float*)d_out;

    cudaFuncSetAttribute(gemm_hmma<0>, cudaFuncAttributeMaxDynamicSharedMemorySize, GEMM_SMEM);
    cudaFuncSetAttribute(gemm_hmma<1>, cudaFuncAttributeMaxDynamicSharedMemorySize, GEMM_SMEM);

    prep_kernel<<<512, 256>>>(in_w, out_w, A_log, Bp, Cp, log_dt);
    ln_kernel<<<MR, 256>>>(x, ln_g, ln_b);
    gemm_hmma<0><<<dim3(2*DM/128, MR/128), 256, GEMM_SMEM>>>(in_b, nullptr, nullptr);
    ssm_pass1<<<dim3(DM/128, NCH, NB), 128>>>();
    ssm_pass2<<<(NB*DM*DS)/256, 256>>>();
    ssm_pass3<<<dim3(DM/128, NCH, NB), 128>>>();
    gemm_hmma<1><<<dim3(DM/128, MR/128), 256, GEMM_SMEM>>>(out_b, x, outp);
}

// round 14
// speedup vs baseline: 3.8915x; 1.0173x over previous
#include <cuda_runtime.h>
#include <cuda_bf16.h>
#include <cstdint>

#define DM 1024
#define DS 16
#define NB 4
#define LS 2048
#define MR (NB*LS)      // 8192 rows
#define LC 32           // scan chunk length
#define NCH (LS/LC)     // 64 chunks

// ---------------- scratch (device globals; no allocations) ----------------
__device__ __align__(256) __nv_bfloat16 g_xn[MR*DM];     // layernormed x (bf16)
__device__ __align__(256) __nv_bfloat16 g_w1[2*DM*DM];   // in_w bf16
__device__ __align__(256) __nv_bfloat16 g_w2[DM*DM];     // out_w bf16
__device__ __align__(256) __nv_bfloat16 g_xproj[MR*DM];  // ssm input u
__device__ __align__(256) __nv_bfloat16 g_zs[MR*DM];     // silu(z)
__device__ __align__(256) __nv_bfloat16 g_gated[MR*DM];  // y * silu(z)
__device__ __align__(256) float g_Abar[DM*DS];
__device__ __align__(256) float g_cbdt[DM*DS];
__device__ __align__(256) float g_Apow[DM*DS];           // Abar^LC
__device__ __align__(256) float g_F[NCH*NB*DM*DS];       // chunk-local end states
__device__ __align__(256) float g_Sin[NCH*NB*DM*DS];     // chunk incoming states

// ---------------- PTX helpers ----------------
__device__ __forceinline__ void cp16(uint32_t s, const void* g){
    asm volatile("cp.async.cg.shared.global [%0], [%1], 16;\n" :: "r"(s), "l"(g));
}
#define LDSM4(v, addr) \
    asm volatile("ldmatrix.sync.aligned.m8n8.x4.shared.b16 {%0,%1,%2,%3}, [%4];" \
        : "=r"((v)[0]), "=r"((v)[1]), "=r"((v)[2]), "=r"((v)[3]) : "r"(addr))
#define MMA16816(d, a, b0, b1) \
    asm volatile("mma.sync.aligned.m16n8k16.row.col.f32.bf16.bf16.f32 " \
        "{%0,%1,%2,%3},{%4,%5,%6,%7},{%8,%9},{%0,%1,%2,%3};" \
        : "+f"((d)[0]), "+f"((d)[1]), "+f"((d)[2]), "+f"((d)[3]) \
        : "r"((a)[0]), "r"((a)[1]), "r"((a)[2]), "r"((a)[3]), "r"(b0), "r"(b1))

// ---------------- prep: weight bf16 cast (vectorized) + SSM params ----------
__global__ void prep_kernel(const float* __restrict__ in_w, const float* __restrict__ out_w,
                            const float* __restrict__ A_log, const float* __restrict__ Bp,
                            const float* __restrict__ Cp, const float* __restrict__ log_dt){
    const int n1 = 2*DM*DM/4, n2 = DM*DM/4, n3 = DM*DS;
    int stride = gridDim.x*blockDim.x;
    for(int i = blockIdx.x*blockDim.x + threadIdx.x; i < n1 + n2 + n3; i += stride){
        if(i < n1 + n2){
            const float* src = (i < n1) ? in_w : out_w;
            int j = (i < n1) ? i : i - n1;
            float4 v = reinterpret_cast<const float4*>(src)[j];
            __nv_bfloat162 p0 = __floats2bfloat162_rn(v.x, v.y);
            __nv_bfloat162 p1 = __floats2bfloat162_rn(v.z, v.w);
            uint2 pk; pk.x = *(uint32_t*)&p0; pk.y = *(uint32_t*)&p1;
            if(i < n1) reinterpret_cast<uint2*>(g_w1)[j] = pk;
            else       reinterpret_cast<uint2*>(g_w2)[j] = pk;
        } else {
            int j = i - n1 - n2;                  // over DM*DS
            int d = j >> 4;
            float dt = fminf(fmaxf(expf(log_dt[d]), 1e-4f), 1.0f);
            float Ab = expf(-expf(A_log[j]) * dt);
            Ab = fminf(fmaxf(Ab, 1e-8f), 1.0f - 1e-8f);
            g_Abar[j] = Ab;
            g_cbdt[j] = Cp[j] * Bp[j] * dt;
            float p = Ab;
            #pragma unroll
            for(int q = 0; q < 5; q++) p = p*p;   // Abar^32 (LC=32)
            g_Apow[j] = p;
        }
    }
}

// ---------------- layernorm (row = one block) ----------------
__global__ void ln_kernel(const float* __restrict__ x, const float* __restrict__ g,
                          const float* __restrict__ b){
    int r = blockIdx.x, t = threadIdx.x;
    float4 v = reinterpret_cast<const float4*>(x + (size_t)r*DM)[t];
    float s = v.x+v.y+v.z+v.w;
    float q = v.x*v.x + v.y*v.y + v.z*v.z + v.w*v.w;
    #pragma unroll
    for(int o = 16; o; o >>= 1){
        s += __shfl_xor_sync(0xffffffffu, s, o);
        q += __shfl_xor_sync(0xffffffffu, q, o);
    }
    __shared__ float ss[8], qs[8];
    int w = t >> 5, lane = t & 31;
    if(lane == 0){ ss[w] = s; qs[w] = q; }
    __syncthreads();
    s = 0.f; q = 0.f;
    #pragma unroll
    for(int i = 0; i < 8; i++){ s += ss[i]; q += qs[i]; }
    float mu  = s * (1.0f/DM);
    float var = q * (1.0f/DM) - mu*mu;
    float rs  = rsqrtf(var + 1e-5f);
    float4 gv = reinterpret_cast<const float4*>(g)[t];
    float4 bv = reinterpret_cast<const float4*>(b)[t];
    float o0 = (v.x-mu)*rs*gv.x + bv.x;
    float o1 = (v.y-mu)*rs*gv.y + bv.y;
    float o2 = (v.z-mu)*rs*gv.z + bv.z;
    float o3 = (v.w-mu)*rs*gv.w + bv.w;
    __nv_bfloat162 p0 = __floats2bfloat162_rn(o0, o1);
    __nv_bfloat162 p1 = __floats2bfloat162_rn(o2, o3);
    uint2 pk; pk.x = *(uint32_t*)&p0; pk.y = *(uint32_t*)&p1;
    reinterpret_cast<uint2*>(g_xn + (size_t)r*DM)[t] = pk;
}

// ---------------- HMMA GEMM: 128x128 tile, K=64 stages, 3-stage pipeline -----
// Epilogue stages f32 tile in smem (pitch 136 floats) -> coalesced stores.
// MODE 0 x-half additionally computes the 4 chunk-end scan states (fused pass1).
#define STG_BYTES 32768
#define NSTG 3
#define EPI_PITCH 136
#define GEMM_SMEM (NSTG*STG_BYTES + 128)     // 98432; epilogue needs 128*136*4=69632

template<int MODE>
__global__ void __launch_bounds__(256, 2) gemm_hmma(const float* __restrict__ bias,
                                                    const float* __restrict__ resid,
                                                    float* __restrict__ outp){
    constexpr int K = DM, KB = K*2;
    const __nv_bfloat16* __restrict__ Am = (MODE==0) ? g_xn : g_gated;
    const __nv_bfloat16* __restrict__ Bm = (MODE==0) ? g_w1 : g_w2;

    extern __shared__ char smem_dyn[];
    uint32_t sraw  = (uint32_t)__cvta_generic_to_shared(smem_dyn);
    uint32_t sbase = (sraw + 127) & ~127u;
    float*   epi   = (float*)(smem_dyn + (sbase - sraw));   // generic view of sbase

    int t = threadIdx.x, lane = t & 31, wid = t >> 5;
    int wm = wid >> 1, wn = wid & 1;             // 4 x 2 warps over 128x128
    int m0 = blockIdx.y * 128, n0 = blockIdx.x * 128;

    // -------- hoisted load addressing: 4 A-chunks + 4 B-chunks per thread ----
    uint32_t soff[4];
    const char* pA[4];
    const char* pB[4];
    #pragma unroll
    for(int i = 0; i < 4; i++){
        int idx = t + i*256;
        int r = idx >> 3, c = idx & 7;
        soff[i] = (uint32_t)(r*128 + ((c ^ (r & 7)) << 4));
        pA[i] = (const char*)Am + (size_t)(m0 + r)*KB + c*16;
        pB[i] = (const char*)Bm + (size_t)(n0 + r)*KB + c*16;
    }

    auto load = [&](uint32_t stg){
        #pragma unroll
        for(int i = 0; i < 4; i++){
            cp16(stg + soff[i],          pA[i]);
            cp16(stg + 16384 + soff[i],  pB[i]);
            pA[i] += 128; pB[i] += 128;
        }
    };

    float acc[2][8][4];
    #pragma unroll
    for(int i=0;i<2;i++)
    #pragma unroll
    for(int j=0;j<8;j++)
    #pragma unroll
    for(int q=0;q<4;q++) acc[i][j][q] = 0.f;

    load(sbase + 0*STG_BYTES); asm volatile("cp.async.commit_group;");
    load(sbase + 1*STG_BYTES); asm volatile("cp.async.commit_group;");

    // -------- hoisted fragment addressing ------------------------------------
    int la_r = lane & 15, la_k = lane >> 4;
    uint32_t sw  = (uint32_t)(la_r & 7);
    uint32_t kx[4];
    #pragma unroll
    for(int kg = 0; kg < 4; kg++)
        kx[kg] = (((uint32_t)(kg*2 + la_k)) ^ sw) << 4;
    uint32_t aoff = (uint32_t)((wm*32 + la_r) * 128);
    uint32_t boff = (uint32_t)((wn*64 + la_r) * 128) + 16384;

    const int NCHK = K/64;                        // 16 chunks
    #pragma unroll 1
    for(int k = 0; k < NCHK; k++){
        uint32_t stg = sbase + (uint32_t)((k % 3) * STG_BYTES);
        asm volatile("cp.async.wait_group 1;");
        __syncthreads();
        if(k + 2 < NCHK) load(sbase + (uint32_t)(((k+2) % 3) * STG_BYTES));
        asm volatile("cp.async.commit_group;");
        uint32_t smA = stg + aoff;
        uint32_t smB = stg + boff;
        #pragma unroll
        for(int kg = 0; kg < 4; kg++){            // 4 x k16 between barriers
            uint32_t kc = kx[kg];
            uint32_t a[2][4], b[4][4];
            #pragma unroll
            for(int mi = 0; mi < 2; mi++) LDSM4(a[mi], smA + mi*2048 + kc);
            #pragma unroll
            for(int ng = 0; ng < 4; ng++) LDSM4(b[ng], smB + ng*2048 + kc);
            #pragma unroll
            for(int mi = 0; mi < 2; mi++)
            #pragma unroll
            for(int ng = 0; ng < 4; ng++){
                MMA16816(acc[mi][2*ng],   a[mi], b[ng][0], b[ng][2]);
                MMA16816(acc[mi][2*ng+1], a[mi], b[ng][1], b[ng][3]);
            }
        }
    }
    asm volatile("cp.async.wait_group 0;");
    __syncthreads();                              // mainloop smem dead; reuse for staging

    // -------- stage f32 tile (with bias, + silu for z-half) ------------------
    int grp = lane >> 2, c2 = (lane & 3) * 2;
    const bool zh = (MODE == 0) && (n0 >= DM);
    #pragma unroll
    for(int mi = 0; mi < 2; mi++){
        #pragma unroll
        for(int ni = 0; ni < 8; ni++){
            int rl = wm*32 + mi*16 + grp;
            int cl = wn*64 + ni*8 + c2;
            float b0 = __ldg(&bias[n0 + cl]), b1 = __ldg(&bias[n0 + cl + 1]);
            #pragma unroll
            for(int h = 0; h < 2; h++){
                float v0 = acc[mi][ni][2*h+0] + b0;
                float v1 = acc[mi][ni][2*h+1] + b1;
                if(zh){
                    v0 = v0 / (1.f + __expf(-v0));
                    v1 = v1 / (1.f + __expf(-v1));
                }
                float2 p; p.x = v0; p.y = v1;
                *(float2*)&epi[(rl + h*8)*EPI_PITCH + cl] = p;
            }
        }
    }
    __syncthreads();

    if(MODE == 0){
        // coalesced bf16 write-out: 128 rows x 16 x 16B
        __nv_bfloat16* dstb = zh ? g_zs : g_xproj;
        int colb = n0 - (zh ? DM : 0);
        #pragma unroll
        for(int i = 0; i < 8; i++){
            int idx = t + i*256;
            int r = idx >> 4, c = idx & 15;
            const float4 f0 = *(const float4*)&epi[r*EPI_PITCH + c*8];
            const float4 f1 = *(const float4*)&epi[r*EPI_PITCH + c*8 + 4];
            __nv_bfloat162 h0 = __floats2bfloat162_rn(f0.x, f0.y);
            __nv_bfloat162 h1 = __floats2bfloat162_rn(f0.z, f0.w);
            __nv_bfloat162 h2 = __floats2bfloat162_rn(f1.x, f1.y);
            __nv_bfloat162 h3 = __floats2bfloat162_rn(f1.z, f1.w);
            uint4 pk; pk.x = *(uint32_t*)&h0; pk.y = *(uint32_t*)&h1;
            pk.z = *(uint32_t*)&h2; pk.w = *(uint32_t*)&h3;
            *(uint4*)&dstb[(size_t)(m0 + r)*DM + colb + c*8] = pk;
        }
        // fused pass1: 4 chunk-end states per column (x-half only)
        if(!zh){
            int bb = m0 >> 11;                    // /LS
            int cbase = (m0 & (LS-1)) >> 5;       // /LC
            #pragma unroll
            for(int task = t; task < 512; task += 256){
                int cc = task >> 7, col = task & 127;
                int d = n0 + col;
                float Aa[DS], s[DS];
                const float4* A4 = reinterpret_cast<const float4*>(g_Abar + d*DS);
                #pragma unroll
                for(int j=0;j<4;j++){
                    float4 v=A4[j];
                    Aa[4*j]=v.x; Aa[4*j+1]=v.y; Aa[4*j+2]=v.z; Aa[4*j+3]=v.w;
                }
                #pragma unroll
                for(int n=0;n<DS;n++) s[n] = 0.f;
                const float* up = &epi[(cc*32)*EPI_PITCH + col];
                #pragma unroll 8
                for(int row = 0; row < LC; ++row){
                    float uv = up[row*EPI_PITCH];
                    #pragma unroll
                    for(int n=0;n<DS;n++) s[n] = fmaf(Aa[n], s[n], uv);
                }
                float4* F4 = reinterpret_cast<float4*>(
                    g_F + (size_t)(((cbase+cc)*NB + bb)*DM + d)*DS);
                #pragma unroll
                for(int j=0;j<4;j++){
                    float4 v; v.x=s[4*j]; v.y=s[4*j+1]; v.z=s[4*j+2]; v.w=s[4*j+3];
                    F4[j]=v;
                }
            }
        }
    } else {
        // coalesced f32 write-out with resid + clip: 128 rows x 32 float4
        #pragma unroll
        for(int i = 0; i < 16; i++){
            int idx = t + i*256;
            int r = idx >> 5, c = idx & 31;
            size_t gi = (size_t)(m0 + r)*DM + n0 + c*4;
            float4 v = *(const float4*)&epi[r*EPI_PITCH + c*4];
            float4 rv = *(const float4*)&resid[gi];
            v.x = fminf(fmaxf(v.x + rv.x, -10.f), 10.f);
            v.y = fminf(fmaxf(v.y + rv.y, -10.f), 10.f);
            v.z = fminf(fmaxf(v.z + rv.z, -10.f), 10.f);
            v.w = fminf(fmaxf(v.w + rv.w, -10.f), 10.f);
            *(float4*)&outp[gi] = v;
        }
    }
}

// ---------------- SSM scan passes 2 & 3 (validated) ----------------
__global__ void ssm_pass2(){
    int i = blockIdx.x*blockDim.x + threadIdx.x;      // over NB*DM*DS = 65536
    float Ap = g_Apow[i & (DM*DS - 1)];
    float s = 0.f;
    #pragma unroll 8
    for(int c = 0; c < NCH; c++){
        g_Sin[c*(NB*DM*DS) + i] = s;
        s = fmaf(Ap, s, g_F[c*(NB*DM*DS) + i]);
    }
}

__global__ void ssm_pass3(){
    __shared__ __align__(16) __nv_bfloat16 su[LC*128];   // 8KB u
    __shared__ __align__(16) __nv_bfloat16 sz[LC*128];   // 8KB silu(z)
    __shared__ __align__(16) __nv_bfloat16 so[LC*128];   // 8KB out
    int t = threadIdx.x;
    int c = blockIdx.y, b = blockIdx.z;
    int d = blockIdx.x*128 + t;
    size_t goff = (size_t)(b*LS + c*LC)*DM + blockIdx.x*128;
    const char* gu = (const char*)(g_xproj + goff);
    const char* gz = (const char*)(g_zs + goff);
    uint32_t sbu = (uint32_t)__cvta_generic_to_shared(su);
    uint32_t sbz = (uint32_t)__cvta_generic_to_shared(sz);
    #pragma unroll
    for(int i = 0; i < 4; i++){
        int idx = t + i*128;
        size_t go = (size_t)(idx >> 4)*(DM*2) + (idx & 15)*16;
        cp16(sbu + (uint32_t)idx*16, gu + go);
        cp16(sbz + (uint32_t)idx*16, gz + go);
    }
    asm volatile("cp.async.commit_group;");

    float Aa[DS], cb[DS], s[DS];
    const float4* A4 = reinterpret_cast<const float4*>(g_Abar + d*DS);
    const float4* C4 = reinterpret_cast<const float4*>(g_cbdt + d*DS);
    const float4* S4 = reinterpret_cast<const float4*>(g_Sin + (size_t)c*(NB*DM*DS) + (size_t)(b*DM + d)*DS);
    #pragma unroll
    for(int j=0;j<4;j++){
        float4 va=A4[j]; Aa[4*j]=va.x; Aa[4*j+1]=va.y; Aa[4*j+2]=va.z; Aa[4*j+3]=va.w;
        float4 vc=C4[j]; cb[4*j]=vc.x; cb[4*j+1]=vc.y; cb[4*j+2]=vc.z; cb[4*j+3]=vc.w;
        float4 vs=S4[j]; s[4*j]=vs.x;  s[4*j+1]=vs.y;  s[4*j+2]=vs.z;  s[4*j+3]=vs.w;
    }
    asm volatile("cp.async.wait_group 0;");
    __syncthreads();
    #pragma unroll 4
    for(int tt = 0; tt < LC; ++tt){
        float uv = __bfloat162float(su[tt*128 + t]);
        #pragma unroll
        for(int n=0;n<DS;n++) s[n] = fmaf(Aa[n], s[n], uv);
        float y = 0.f;
        #pragma unroll
        for(int n=0;n<DS;n++) y = fmaf(cb[n], s[n], y);
        float zv = __bfloat162float(sz[tt*128 + t]);
        so[tt*128 + t] = __float2bfloat16_rn(y * zv);
    }
    __syncthreads();
    char* gg = (char*)(g_gated + goff);
    #pragma unroll
    for(int i = 0; i < 4; i++){                 // coalesced 16B stores
        int idx = t + i*128;
        *reinterpret_cast<uint4*>(gg + (size_t)(idx >> 4)*(DM*2) + (idx & 15)*16)
            = *reinterpret_cast<const uint4*>(reinterpret_cast<const char*>(so) + idx*16);
    }
}

// ---------------- launch ----------------
extern "C" void kernel_launch(void* const* d_in, const int* in_sizes, int n_in,
                              void* d_out, int out_size){
    const float* x      = (const float*)d_in[0];
    const float* A_log  = (const float*)d_in[1];
    const float* Bp     = (const float*)d_in[2];
    const float* Cp     = (const float*)d_in[3];
    const float* log_dt = (const float*)d_in[4];
    const float* in_w   = (const float*)d_in[5];
    const float* in_b   = (const float*)d_in[6];
    const float* out_w  = (const float*)d_in[7];
    const float* out_b  = (const float*)d_in[8];
    const float* ln_g   = (const float*)d_in[9];
    const float* ln_b   = (const float*)d_in[10];
    float* outp = (float*)d_out;

    cudaFuncSetAttribute(gemm_hmma<0>, cudaFuncAttributeMaxDynamicSharedMemorySize, GEMM_SMEM);
    cudaFuncSetAttribute(gemm_hmma<1>, cudaFuncAttributeMaxDynamicSharedMemorySize, GEMM_SMEM);

    prep_kernel<<<512, 256>>>(in_w, out_w, A_log, Bp, Cp, log_dt);
    ln_kernel<<<MR, 256>>>(x, ln_g, ln_b);
    gemm_hmma<0><<<dim3(2*DM/128, MR/128), 256, GEMM_SMEM>>>(in_b, nullptr, nullptr);
    ssm_pass2<<<(NB*DM*DS)/256, 256>>>();
    ssm_pass3<<<dim3(DM/128, NCH, NB), 128>>>();
    gemm_hmma<1><<<dim3(DM/128, MR/128), 256, GEMM_SMEM>>>(out_b, x, outp);
}

// round 15
// speedup vs baseline: 4.0028x; 1.0286x over previous
#include <cuda_runtime.h>
#include <cuda_bf16.h>
#include <cstdint>

#define DM 1024
#define DS 16
#define NB 4
#define LS 2048
#define MR (NB*LS)      // 8192 rows
#define LC 32           // scan chunk length
#define NCH (LS/LC)     // 64 chunks
#define NEL (NB*DM*DS)  // 65536 state elements
#define SEGL 8          // chunks per segment
#define NSEG (NCH/SEGL) // 8 segments

// ---------------- scratch (device globals; no allocations) ----------------
__device__ __align__(256) __nv_bfloat16 g_xn[MR*DM];     // layernormed x (bf16)
__device__ __align__(256) __nv_bfloat16 g_w1[2*DM*DM];   // in_w bf16
__device__ __align__(256) __nv_bfloat16 g_w2[DM*DM];     // out_w bf16
__device__ __align__(256) __nv_bfloat16 g_xproj[MR*DM];  // ssm input u
__device__ __align__(256) __nv_bfloat16 g_zs[MR*DM];     // silu(z)
__device__ __align__(256) __nv_bfloat16 g_gated[MR*DM];  // y * silu(z)
__device__ __align__(256) float g_Abar[DM*DS];
__device__ __align__(256) float g_cbdt[DM*DS];
__device__ __align__(256) float g_Apow[DM*DS];           // Abar^LC
__device__ __align__(256) float g_F[NCH*NEL];            // chunk-local end states
__device__ __align__(256) float g_Sin[NCH*NEL];          // chunk incoming (seg-local)
__device__ __align__(256) float g_Seg[NSEG*NEL];         // segment end states
__device__ __align__(256) float g_SegIn[NSEG*NEL];       // segment incoming states

// ---------------- PTX helpers ----------------
__device__ __forceinline__ void cp16(uint32_t s, const void* g){
    asm volatile("cp.async.cg.shared.global [%0], [%1], 16;\n" :: "r"(s), "l"(g));
}
#define LDSM4(v, addr) \
    asm volatile("ldmatrix.sync.aligned.m8n8.x4.shared.b16 {%0,%1,%2,%3}, [%4];" \
        : "=r"((v)[0]), "=r"((v)[1]), "=r"((v)[2]), "=r"((v)[3]) : "r"(addr))
#define MMA16816(d, a, b0, b1) \
    asm volatile("mma.sync.aligned.m16n8k16.row.col.f32.bf16.bf16.f32 " \
        "{%0,%1,%2,%3},{%4,%5,%6,%7},{%8,%9},{%0,%1,%2,%3};" \
        : "+f"((d)[0]), "+f"((d)[1]), "+f"((d)[2]), "+f"((d)[3]) \
        : "r"((a)[0]), "r"((a)[1]), "r"((a)[2]), "r"((a)[3]), "r"(b0), "r"(b1))

// ---------------- prep: weight bf16 cast (vectorized) + SSM params ----------
__global__ void prep_kernel(const float* __restrict__ in_w, const float* __restrict__ out_w,
                            const float* __restrict__ A_log, const float* __restrict__ Bp,
                            const float* __restrict__ Cp, const float* __restrict__ log_dt){
    const int n1 = 2*DM*DM/4, n2 = DM*DM/4, n3 = DM*DS;
    int stride = gridDim.x*blockDim.x;
    for(int i = blockIdx.x*blockDim.x + threadIdx.x; i < n1 + n2 + n3; i += stride){
        if(i < n1 + n2){
            const float* src = (i < n1) ? in_w : out_w;
            int j = (i < n1) ? i : i - n1;
            float4 v = reinterpret_cast<const float4*>(src)[j];
            __nv_bfloat162 p0 = __floats2bfloat162_rn(v.x, v.y);
            __nv_bfloat162 p1 = __floats2bfloat162_rn(v.z, v.w);
            uint2 pk; pk.x = *(uint32_t*)&p0; pk.y = *(uint32_t*)&p1;
            if(i < n1) reinterpret_cast<uint2*>(g_w1)[j] = pk;
            else       reinterpret_cast<uint2*>(g_w2)[j] = pk;
        } else {
            int j = i - n1 - n2;                  // over DM*DS
            int d = j >> 4;
            float dt = fminf(fmaxf(expf(log_dt[d]), 1e-4f), 1.0f);
            float Ab = expf(-expf(A_log[j]) * dt);
            Ab = fminf(fmaxf(Ab, 1e-8f), 1.0f - 1e-8f);
            g_Abar[j] = Ab;
            g_cbdt[j] = Cp[j] * Bp[j] * dt;
            float p = Ab;
            #pragma unroll
            for(int q = 0; q < 5; q++) p = p*p;   // Abar^32 (LC=32)
            g_Apow[j] = p;
        }
    }
}

// ---------------- layernorm (row = one block) ----------------
__global__ void ln_kernel(const float* __restrict__ x, const float* __restrict__ g,
                          const float* __restrict__ b){
    int r = blockIdx.x, t = threadIdx.x;
    float4 v = reinterpret_cast<const float4*>(x + (size_t)r*DM)[t];
    float s = v.x+v.y+v.z+v.w;
    float q = v.x*v.x + v.y*v.y + v.z*v.z + v.w*v.w;
    #pragma unroll
    for(int o = 16; o; o >>= 1){
        s += __shfl_xor_sync(0xffffffffu, s, o);
        q += __shfl_xor_sync(0xffffffffu, q, o);
    }
    __shared__ float ss[8], qs[8];
    int w = t >> 5, lane = t & 31;
    if(lane == 0){ ss[w] = s; qs[w] = q; }
    __syncthreads();
    s = 0.f; q = 0.f;
    #pragma unroll
    for(int i = 0; i < 8; i++){ s += ss[i]; q += qs[i]; }
    float mu  = s * (1.0f/DM);
    float var = q * (1.0f/DM) - mu*mu;
    float rs  = rsqrtf(var + 1e-5f);
    float4 gv = reinterpret_cast<const float4*>(g)[t];
    float4 bv = reinterpret_cast<const float4*>(b)[t];
    float o0 = (v.x-mu)*rs*gv.x + bv.x;
    float o1 = (v.y-mu)*rs*gv.y + bv.y;
    float o2 = (v.z-mu)*rs*gv.z + bv.z;
    float o3 = (v.w-mu)*rs*gv.w + bv.w;
    __nv_bfloat162 p0 = __floats2bfloat162_rn(o0, o1);
    __nv_bfloat162 p1 = __floats2bfloat162_rn(o2, o3);
    uint2 pk; pk.x = *(uint32_t*)&p0; pk.y = *(uint32_t*)&p1;
    reinterpret_cast<uint2*>(g_xn + (size_t)r*DM)[t] = pk;
}

// ---------------- HMMA GEMM: 128x128 tile, K=64 stages, 3-stage pipeline -----
// Epilogue stages f32 tile in smem (pitch 136 floats) -> coalesced stores.
// MODE 0 x-half additionally computes the 4 chunk-end scan states (fused pass1).
#define STG_BYTES 32768
#define NSTG 3
#define EPI_PITCH 136
#define GEMM_SMEM (NSTG*STG_BYTES + 128)     // 98432; epilogue needs 128*136*4=69632

template<int MODE>
__global__ void __launch_bounds__(256, 2) gemm_hmma(const float* __restrict__ bias,
                                                    const float* __restrict__ resid,
                                                    float* __restrict__ outp){
    constexpr int K = DM, KB = K*2;
    const __nv_bfloat16* __restrict__ Am = (MODE==0) ? g_xn : g_gated;
    const __nv_bfloat16* __restrict__ Bm = (MODE==0) ? g_w1 : g_w2;

    extern __shared__ char smem_dyn[];
    uint32_t sraw  = (uint32_t)__cvta_generic_to_shared(smem_dyn);
    uint32_t sbase = (sraw + 127) & ~127u;
    float*   epi   = (float*)(smem_dyn + (sbase - sraw));   // generic view of sbase

    int t = threadIdx.x, lane = t & 31, wid = t >> 5;
    int wm = wid >> 1, wn = wid & 1;             // 4 x 2 warps over 128x128
    int m0 = blockIdx.y * 128, n0 = blockIdx.x * 128;

    // -------- hoisted load addressing: 4 A-chunks + 4 B-chunks per thread ----
    uint32_t soff[4];
    const char* pA[4];
    const char* pB[4];
    #pragma unroll
    for(int i = 0; i < 4; i++){
        int idx = t + i*256;
        int r = idx >> 3, c = idx & 7;
        soff[i] = (uint32_t)(r*128 + ((c ^ (r & 7)) << 4));
        pA[i] = (const char*)Am + (size_t)(m0 + r)*KB + c*16;
        pB[i] = (const char*)Bm + (size_t)(n0 + r)*KB + c*16;
    }

    auto load = [&](uint32_t stg){
        #pragma unroll
        for(int i = 0; i < 4; i++){
            cp16(stg + soff[i],          pA[i]);
            cp16(stg + 16384 + soff[i],  pB[i]);
            pA[i] += 128; pB[i] += 128;
        }
    };

    float acc[2][8][4];
    #pragma unroll
    for(int i=0;i<2;i++)
    #pragma unroll
    for(int j=0;j<8;j++)
    #pragma unroll
    for(int q=0;q<4;q++) acc[i][j][q] = 0.f;

    load(sbase + 0*STG_BYTES); asm volatile("cp.async.commit_group;");
    load(sbase + 1*STG_BYTES); asm volatile("cp.async.commit_group;");

    // -------- hoisted fragment addressing ------------------------------------
    int la_r = lane & 15, la_k = lane >> 4;
    uint32_t sw  = (uint32_t)(la_r & 7);
    uint32_t kx[4];
    #pragma unroll
    for(int kg = 0; kg < 4; kg++)
        kx[kg] = (((uint32_t)(kg*2 + la_k)) ^ sw) << 4;
    uint32_t aoff = (uint32_t)((wm*32 + la_r) * 128);
    uint32_t boff = (uint32_t)((wn*64 + la_r) * 128) + 16384;

    const int NCHK = K/64;                        // 16 chunks
    #pragma unroll 1
    for(int k = 0; k < NCHK; k++){
        uint32_t stg = sbase + (uint32_t)((k % 3) * STG_BYTES);
        asm volatile("cp.async.wait_group 1;");
        __syncthreads();
        if(k + 2 < NCHK) load(sbase + (uint32_t)(((k+2) % 3) * STG_BYTES));
        asm volatile("cp.async.commit_group;");
        uint32_t smA = stg + aoff;
        uint32_t smB = stg + boff;
        #pragma unroll
        for(int kg = 0; kg < 4; kg++){            // 4 x k16 between barriers
            uint32_t kc = kx[kg];
            uint32_t a[2][4], b[4][4];
            #pragma unroll
            for(int mi = 0; mi < 2; mi++) LDSM4(a[mi], smA + mi*2048 + kc);
            #pragma unroll
            for(int ng = 0; ng < 4; ng++) LDSM4(b[ng], smB + ng*2048 + kc);
            #pragma unroll
            for(int mi = 0; mi < 2; mi++)
            #pragma unroll
            for(int ng = 0; ng < 4; ng++){
                MMA16816(acc[mi][2*ng],   a[mi], b[ng][0], b[ng][2]);
                MMA16816(acc[mi][2*ng+1], a[mi], b[ng][1], b[ng][3]);
            }
        }
    }
    asm volatile("cp.async.wait_group 0;");
    __syncthreads();                              // mainloop smem dead; reuse for staging

    // -------- stage f32 tile (with bias, + silu for z-half) ------------------
    int grp = lane >> 2, c2 = (lane & 3) * 2;
    const bool zh = (MODE == 0) && (n0 >= DM);
    #pragma unroll
    for(int mi = 0; mi < 2; mi++){
        #pragma unroll
        for(int ni = 0; ni < 8; ni++){
            int rl = wm*32 + mi*16 + grp;
            int cl = wn*64 + ni*8 + c2;
            float b0 = __ldg(&bias[n0 + cl]), b1 = __ldg(&bias[n0 + cl + 1]);
            #pragma unroll
            for(int h = 0; h < 2; h++){
                float v0 = acc[mi][ni][2*h+0] + b0;
                float v1 = acc[mi][ni][2*h+1] + b1;
                if(zh){
                    v0 = v0 / (1.f + __expf(-v0));
                    v1 = v1 / (1.f + __expf(-v1));
                }
                float2 p; p.x = v0; p.y = v1;
                *(float2*)&epi[(rl + h*8)*EPI_PITCH + cl] = p;
            }
        }
    }
    __syncthreads();

    if(MODE == 0){
        // coalesced bf16 write-out: 128 rows x 16 x 16B
        __nv_bfloat16* dstb = zh ? g_zs : g_xproj;
        int colb = n0 - (zh ? DM : 0);
        #pragma unroll
        for(int i = 0; i < 8; i++){
            int idx = t + i*256;
            int r = idx >> 4, c = idx & 15;
            const float4 f0 = *(const float4*)&epi[r*EPI_PITCH + c*8];
            const float4 f1 = *(const float4*)&epi[r*EPI_PITCH + c*8 + 4];
            __nv_bfloat162 h0 = __floats2bfloat162_rn(f0.x, f0.y);
            __nv_bfloat162 h1 = __floats2bfloat162_rn(f0.z, f0.w);
            __nv_bfloat162 h2 = __floats2bfloat162_rn(f1.x, f1.y);
            __nv_bfloat162 h3 = __floats2bfloat162_rn(f1.z, f1.w);
            uint4 pk; pk.x = *(uint32_t*)&h0; pk.y = *(uint32_t*)&h1;
            pk.z = *(uint32_t*)&h2; pk.w = *(uint32_t*)&h3;
            *(uint4*)&dstb[(size_t)(m0 + r)*DM + colb + c*8] = pk;
        }
        // fused pass1: 4 chunk-end states per column (x-half only)
        if(!zh){
            int bb = m0 >> 11;                    // /LS
            int cbase = (m0 & (LS-1)) >> 5;       // /LC
            #pragma unroll
            for(int task = t; task < 512; task += 256){
                int cc = task >> 7, col = task & 127;
                int d = n0 + col;
                float Aa[DS], s[DS];
                const float4* A4 = reinterpret_cast<const float4*>(g_Abar + d*DS);
                #pragma unroll
                for(int j=0;j<4;j++){
                    float4 v=A4[j];
                    Aa[4*j]=v.x; Aa[4*j+1]=v.y; Aa[4*j+2]=v.z; Aa[4*j+3]=v.w;
                }
                #pragma unroll
                for(int n=0;n<DS;n++) s[n] = 0.f;
                const float* up = &epi[(cc*32)*EPI_PITCH + col];
                #pragma unroll 8
                for(int row = 0; row < LC; ++row){
                    float uv = up[row*EPI_PITCH];
                    #pragma unroll
                    for(int n=0;n<DS;n++) s[n] = fmaf(Aa[n], s[n], uv);
                }
                float4* F4 = reinterpret_cast<float4*>(
                    g_F + (size_t)(((cbase+cc)*NB + bb)*DM + d)*DS);
                #pragma unroll
                for(int j=0;j<4;j++){
                    float4 v; v.x=s[4*j]; v.y=s[4*j+1]; v.z=s[4*j+2]; v.w=s[4*j+3];
                    F4[j]=v;
                }
            }
        }
    } else {
        // coalesced f32 write-out with resid + clip: 128 rows x 32 float4
        #pragma unroll
        for(int i = 0; i < 16; i++){
            int idx = t + i*256;
            int r = idx >> 5, c = idx & 31;
            size_t gi = (size_t)(m0 + r)*DM + n0 + c*4;
            float4 v = *(const float4*)&epi[r*EPI_PITCH + c*4];
            float4 rv = *(const float4*)&resid[gi];
            v.x = fminf(fmaxf(v.x + rv.x, -10.f), 10.f);
            v.y = fminf(fmaxf(v.y + rv.y, -10.f), 10.f);
            v.z = fminf(fmaxf(v.z + rv.z, -10.f), 10.f);
            v.w = fminf(fmaxf(v.w + rv.w, -10.f), 10.f);
            *(float4*)&outp[gi] = v;
        }
    }
}

// ---------------- SSM two-level chunk scan ----------------
// pass2a: segment-local scans, 8x parallelism of the old pass2.
__global__ void ssm_pass2a(){
    int t = threadIdx.x;
    int seg = blockIdx.x >> 8;                      // 8 segments x 256 blocks
    int i = ((blockIdx.x & 255) << 8) + t;          // element 0..NEL-1
    float Ap = g_Apow[i & (DM*DS - 1)];
    float s = 0.f;
    #pragma unroll
    for(int j = 0; j < SEGL; j++){
        int c = seg*SEGL + j;
        g_Sin[(size_t)c*NEL + i] = s;               // segment-LOCAL incoming
        s = fmaf(Ap, s, g_F[(size_t)c*NEL + i]);
    }
    g_Seg[(size_t)seg*NEL + i] = s;                 // segment end-state (zero init)
}

// pass2b: scan the 8 segment totals with decay Apow^SEGL.
__global__ void ssm_pass2b(){
    int i = blockIdx.x*blockDim.x + threadIdx.x;
    float Ap = g_Apow[i & (DM*DS - 1)];
    float p2 = Ap*Ap, p4 = p2*p2, Ap8 = p4*p4;      // Apow^8
    float s = 0.f;
    #pragma unroll
    for(int seg = 0; seg < NSEG; seg++){
        g_SegIn[(size_t)seg*NEL + i] = s;
        s = fmaf(Ap8, s, g_Seg[(size_t)seg*NEL + i]);
    }
}

// pass3: replay chunk with true incoming state = local + Apow^j * SegIn.
__global__ void ssm_pass3(){
    __shared__ __align__(16) __nv_bfloat16 su[LC*128];   // 8KB u
    __shared__ __align__(16) __nv_bfloat16 sz[LC*128];   // 8KB silu(z)
    __shared__ __align__(16) __nv_bfloat16 so[LC*128];   // 8KB out
    int t = threadIdx.x;
    int c = blockIdx.y, b = blockIdx.z;
    int d = blockIdx.x*128 + t;
    size_t goff = (size_t)(b*LS + c*LC)*DM + blockIdx.x*128;
    const char* gu = (const char*)(g_xproj + goff);
    const char* gz = (const char*)(g_zs + goff);
    uint32_t sbu = (uint32_t)__cvta_generic_to_shared(su);
    uint32_t sbz = (uint32_t)__cvta_generic_to_shared(sz);
    #pragma unroll
    for(int i = 0; i < 4; i++){
        int idx = t + i*128;
        size_t go = (size_t)(idx >> 4)*(DM*2) + (idx & 15)*16;
        cp16(sbu + (uint32_t)idx*16, gu + go);
        cp16(sbz + (uint32_t)idx*16, gz + go);
    }
    asm volatile("cp.async.commit_group;");

    int seg = c >> 3, jj = c & 7;
    size_t eoff = (size_t)(b*DM + d)*DS;
    float Aa[DS], cb[DS], s[DS];
    const float4* A4 = reinterpret_cast<const float4*>(g_Abar + d*DS);
    const float4* C4 = reinterpret_cast<const float4*>(g_cbdt + d*DS);
    const float4* P4 = reinterpret_cast<const float4*>(g_Apow + d*DS);
    const float4* S4 = reinterpret_cast<const float4*>(g_Sin   + (size_t)c*NEL   + eoff);
    const float4* G4 = reinterpret_cast<const float4*>(g_SegIn + (size_t)seg*NEL + eoff);
    #pragma unroll
    for(int j=0;j<4;j++){
        float4 va=A4[j]; Aa[4*j]=va.x; Aa[4*j+1]=va.y; Aa[4*j+2]=va.z; Aa[4*j+3]=va.w;
        float4 vc=C4[j]; cb[4*j]=vc.x; cb[4*j+1]=vc.y; cb[4*j+2]=vc.z; cb[4*j+3]=vc.w;
        float4 vs=S4[j]; float4 vg=G4[j]; float4 vp=P4[j];
        float pw[4];
        pw[0]=vp.x; pw[1]=vp.y; pw[2]=vp.z; pw[3]=vp.w;
        float loc[4] = {vs.x, vs.y, vs.z, vs.w};
        float gin[4] = {vg.x, vg.y, vg.z, vg.w};
        #pragma unroll
        for(int q=0;q<4;q++){
            float p1 = pw[q], p2 = p1*p1, p4v = p2*p2;
            float apj = 1.f;
            if(jj & 1) apj *= p1;
            if(jj & 2) apj *= p2;
            if(jj & 4) apj *= p4v;
            s[4*j+q] = fmaf(apj, gin[q], loc[q]);
        }
    }
    asm volatile("cp.async.wait_group 0;");
    __syncthreads();
    #pragma unroll 4
    for(int tt = 0; tt < LC; ++tt){
        float uv = __bfloat162float(su[tt*128 + t]);
        #pragma unroll
        for(int n=0;n<DS;n++) s[n] = fmaf(Aa[n], s[n], uv);
        float y = 0.f;
        #pragma unroll
        for(int n=0;n<DS;n++) y = fmaf(cb[n], s[n], y);
        float zv = __bfloat162float(sz[tt*128 + t]);
        so[tt*128 + t] = __float2bfloat16_rn(y * zv);
    }
    __syncthreads();
    char* gg = (char*)(g_gated + goff);
    #pragma unroll
    for(int i = 0; i < 4; i++){                 // coalesced 16B stores
        int idx = t + i*128;
        *reinterpret_cast<uint4*>(gg + (size_t)(idx >> 4)*(DM*2) + (idx & 15)*16)
            = *reinterpret_cast<const uint4*>(reinterpret_cast<const char*>(so) + idx*16);
    }
}

// ---------------- launch ----------------
extern "C" void kernel_launch(void* const* d_in, const int* in_sizes, int n_in,
                              void* d_out, int out_size){
    const float* x      = (const float*)d_in[0];
    const float* A_log  = (const float*)d_in[1];
    const float* Bp     = (const float*)d_in[2];
    const float* Cp     = (const float*)d_in[3];
    const float* log_dt = (const float*)d_in[4];
    const float* in_w   = (const float*)d_in[5];
    const float* in_b   = (const float*)d_in[6];
    const float* out_w  = (const float*)d_in[7];
    const float* out_b  = (const float*)d_in[8];
    const float* ln_g   = (const float*)d_in[9];
    const float* ln_b   = (const float*)d_in[10];
    float* outp = (float*)d_out;

    cudaFuncSetAttribute(gemm_hmma<0>, cudaFuncAttributeMaxDynamicSharedMemorySize, GEMM_SMEM);
    cudaFuncSetAttribute(gemm_hmma<1>, cudaFuncAttributeMaxDynamicSharedMemorySize, GEMM_SMEM);

    prep_kernel<<<512, 256>>>(in_w, out_w, A_log, Bp, Cp, log_dt);
    ln_kernel<<<MR, 256>>>(x, ln_g, ln_b);
    gemm_hmma<0><<<dim3(2*DM/128, MR/128), 256, GEMM_SMEM>>>(in_b, nullptr, nullptr);
    ssm_pass2a<<<NSEG*256, 256>>>();
    ssm_pass2b<<<NEL/256, 256>>>();
    ssm_pass3<<<dim3(DM/128, NCH, NB), 128>>>();
    gemm_hmma<1><<<dim3(DM/128, MR/128), 256, GEMM_SMEM>>>(out_b, x, outp);
}

// round 16
// speedup vs baseline: 4.1095x; 1.0267x over previous
#include <cuda_runtime.h>
#include <cuda_bf16.h>
#include <cstdint>

#define DM 1024
#define DS 16
#define NB 4
#define LS 2048
#define MR (NB*LS)      // 8192 rows
#define LC 32           // scan chunk length
#define NCH (LS/LC)     // 64 chunks
#define NEL (NB*DM*DS)  // 65536 state elements
#define SEGL 8          // chunks per segment
#define NSEG (NCH/SEGL) // 8 segments

// ---------------- scratch (device globals; no allocations) ----------------
__device__ __align__(256) __nv_bfloat16 g_xn[MR*DM];     // layernormed x (bf16)
__device__ __align__(256) __nv_bfloat16 g_w1[2*DM*DM];   // in_w bf16
__device__ __align__(256) __nv_bfloat16 g_w2[DM*DM];     // out_w bf16
__device__ __align__(256) __nv_bfloat16 g_xproj[MR*DM];  // ssm input u
__device__ __align__(256) __nv_bfloat16 g_zs[MR*DM];     // silu(z)
__device__ __align__(256) __nv_bfloat16 g_gated[MR*DM];  // y * silu(z)
__device__ __align__(256) float g_Abar[DM*DS];
__device__ __align__(256) float g_cbdt[DM*DS];
__device__ __align__(256) float g_Apow[DM*DS];           // Abar^LC
__device__ __align__(256) float g_F[NCH*NEL];            // chunk-local end states
__device__ __align__(256) float g_Sin[NCH*NEL];          // chunk incoming (seg-local)
__device__ __align__(256) float g_Seg[NSEG*NEL];         // segment end states
__device__ __align__(256) float g_SegIn[NSEG*NEL];       // segment incoming states

// ---------------- PTX helpers ----------------
__device__ __forceinline__ void cp16(uint32_t s, const void* g){
    asm volatile("cp.async.cg.shared.global [%0], [%1], 16;\n" :: "r"(s), "l"(g));
}
#define LDSM4(v, addr) \
    asm volatile("ldmatrix.sync.aligned.m8n8.x4.shared.b16 {%0,%1,%2,%3}, [%4];" \
        : "=r"((v)[0]), "=r"((v)[1]), "=r"((v)[2]), "=r"((v)[3]) : "r"(addr))
#define MMA16816(d, a, b0, b1) \
    asm volatile("mma.sync.aligned.m16n8k16.row.col.f32.bf16.bf16.f32 " \
        "{%0,%1,%2,%3},{%4,%5,%6,%7},{%8,%9},{%0,%1,%2,%3};" \
        : "+f"((d)[0]), "+f"((d)[1]), "+f"((d)[2]), "+f"((d)[3]) \
        : "r"((a)[0]), "r"((a)[1]), "r"((a)[2]), "r"((a)[3]), "r"(b0), "r"(b1))

// ---------------- prep: weight bf16 cast (vectorized) + SSM params ----------
__global__ void prep_kernel(const float* __restrict__ in_w, const float* __restrict__ out_w,
                            const float* __restrict__ A_log, const float* __restrict__ Bp,
                            const float* __restrict__ Cp, const float* __restrict__ log_dt){
    const int n1 = 2*DM*DM/4, n2 = DM*DM/4, n3 = DM*DS;
    int stride = gridDim.x*blockDim.x;
    for(int i = blockIdx.x*blockDim.x + threadIdx.x; i < n1 + n2 + n3; i += stride){
        if(i < n1 + n2){
            const float* src = (i < n1) ? in_w : out_w;
            int j = (i < n1) ? i : i - n1;
            float4 v = reinterpret_cast<const float4*>(src)[j];
            __nv_bfloat162 p0 = __floats2bfloat162_rn(v.x, v.y);
            __nv_bfloat162 p1 = __floats2bfloat162_rn(v.z, v.w);
            uint2 pk; pk.x = *(uint32_t*)&p0; pk.y = *(uint32_t*)&p1;
            if(i < n1) reinterpret_cast<uint2*>(g_w1)[j] = pk;
            else       reinterpret_cast<uint2*>(g_w2)[j] = pk;
        } else {
            int j = i - n1 - n2;                  // over DM*DS
            int d = j >> 4;
            float dt = fminf(fmaxf(expf(log_dt[d]), 1e-4f), 1.0f);
            float Ab = expf(-expf(A_log[j]) * dt);
            Ab = fminf(fmaxf(Ab, 1e-8f), 1.0f - 1e-8f);
            g_Abar[j] = Ab;
            g_cbdt[j] = Cp[j] * Bp[j] * dt;
            float p = Ab;
            #pragma unroll
            for(int q = 0; q < 5; q++) p = p*p;   // Abar^32 (LC=32)
            g_Apow[j] = p;
        }
    }
}

// ---------------- layernorm (row = one block) ----------------
__global__ void ln_kernel(const float* __restrict__ x, const float* __restrict__ g,
                          const float* __restrict__ b){
    int r = blockIdx.x, t = threadIdx.x;
    float4 v = reinterpret_cast<const float4*>(x + (size_t)r*DM)[t];
    float s = v.x+v.y+v.z+v.w;
    float q = v.x*v.x + v.y*v.y + v.z*v.z + v.w*v.w;
    #pragma unroll
    for(int o = 16; o; o >>= 1){
        s += __shfl_xor_sync(0xffffffffu, s, o);
        q += __shfl_xor_sync(0xffffffffu, q, o);
    }
    __shared__ float ss[8], qs[8];
    int w = t >> 5, lane = t & 31;
    if(lane == 0){ ss[w] = s; qs[w] = q; }
    __syncthreads();
    s = 0.f; q = 0.f;
    #pragma unroll
    for(int i = 0; i < 8; i++){ s += ss[i]; q += qs[i]; }
    float mu  = s * (1.0f/DM);
    float var = q * (1.0f/DM) - mu*mu;
    float rs  = rsqrtf(var + 1e-5f);
    float4 gv = reinterpret_cast<const float4*>(g)[t];
    float4 bv = reinterpret_cast<const float4*>(b)[t];
    float o0 = (v.x-mu)*rs*gv.x + bv.x;
    float o1 = (v.y-mu)*rs*gv.y + bv.y;
    float o2 = (v.z-mu)*rs*gv.z + bv.z;
    float o3 = (v.w-mu)*rs*gv.w + bv.w;
    __nv_bfloat162 p0 = __floats2bfloat162_rn(o0, o1);
    __nv_bfloat162 p1 = __floats2bfloat162_rn(o2, o3);
    uint2 pk; pk.x = *(uint32_t*)&p0; pk.y = *(uint32_t*)&p1;
    reinterpret_cast<uint2*>(g_xn + (size_t)r*DM)[t] = pk;
}

// ---------------- HMMA GEMM: 128x128 tile, K=64 stages, 3-stage pipeline -----
// Epilogue stages f32 tile in smem (pitch 136 floats) -> coalesced stores.
// MODE 0 x-half additionally computes the 4 chunk-end scan states (fused pass1).
#define STG_BYTES 32768
#define NSTG 3
#define EPI_PITCH 136
#define GEMM_SMEM (NSTG*STG_BYTES + 128)     // 98432; epilogue needs 128*136*4=69632

template<int MODE>
__global__ void __launch_bounds__(256, 2) gemm_hmma(const float* __restrict__ bias,
                                                    const float* __restrict__ resid,
                                                    float* __restrict__ outp){
    constexpr int K = DM, KB = K*2;
    const __nv_bfloat16* __restrict__ Am = (MODE==0) ? g_xn : g_gated;
    const __nv_bfloat16* __restrict__ Bm = (MODE==0) ? g_w1 : g_w2;

    extern __shared__ char smem_dyn[];
    uint32_t sraw  = (uint32_t)__cvta_generic_to_shared(smem_dyn);
    uint32_t sbase = (sraw + 127) & ~127u;
    float*   epi   = (float*)(smem_dyn + (sbase - sraw));   // generic view of sbase

    int t = threadIdx.x, lane = t & 31, wid = t >> 5;
    int wm = wid >> 1, wn = wid & 1;             // 4 x 2 warps over 128x128
    int m0 = blockIdx.y * 128, n0 = blockIdx.x * 128;

    // -------- hoisted load addressing: 4 A-chunks + 4 B-chunks per thread ----
    uint32_t soff[4];
    const char* pA[4];
    const char* pB[4];
    #pragma unroll
    for(int i = 0; i < 4; i++){
        int idx = t + i*256;
        int r = idx >> 3, c = idx & 7;
        soff[i] = (uint32_t)(r*128 + ((c ^ (r & 7)) << 4));
        pA[i] = (const char*)Am + (size_t)(m0 + r)*KB + c*16;
        pB[i] = (const char*)Bm + (size_t)(n0 + r)*KB + c*16;
    }

    auto load = [&](uint32_t stg){
        #pragma unroll
        for(int i = 0; i < 4; i++){
            cp16(stg + soff[i],          pA[i]);
            cp16(stg + 16384 + soff[i],  pB[i]);
            pA[i] += 128; pB[i] += 128;
        }
    };

    float acc[2][8][4];
    #pragma unroll
    for(int i=0;i<2;i++)
    #pragma unroll
    for(int j=0;j<8;j++)
    #pragma unroll
    for(int q=0;q<4;q++) acc[i][j][q] = 0.f;

    load(sbase + 0*STG_BYTES); asm volatile("cp.async.commit_group;");
    load(sbase + 1*STG_BYTES); asm volatile("cp.async.commit_group;");

    // -------- hoisted fragment addressing ------------------------------------
    int la_r = lane & 15, la_k = lane >> 4;
    uint32_t sw  = (uint32_t)(la_r & 7);
    uint32_t kx[4];
    #pragma unroll
    for(int kg = 0; kg < 4; kg++)
        kx[kg] = (((uint32_t)(kg*2 + la_k)) ^ sw) << 4;
    uint32_t aoff = (uint32_t)((wm*32 + la_r) * 128);
    uint32_t boff = (uint32_t)((wn*64 + la_r) * 128) + 16384;

    const int NCHK = K/64;                        // 16 chunks
    #pragma unroll 1
    for(int k = 0; k < NCHK; k++){
        uint32_t stg = sbase + (uint32_t)((k % 3) * STG_BYTES);
        asm volatile("cp.async.wait_group 1;");
        __syncthreads();
        if(k + 2 < NCHK) load(sbase + (uint32_t)(((k+2) % 3) * STG_BYTES));
        asm volatile("cp.async.commit_group;");
        uint32_t smA = stg + aoff;
        uint32_t smB = stg + boff;
        #pragma unroll
        for(int kg = 0; kg < 4; kg++){            // 4 x k16 between barriers
            uint32_t kc = kx[kg];
            uint32_t a[2][4], b[4][4];
            #pragma unroll
            for(int mi = 0; mi < 2; mi++) LDSM4(a[mi], smA + mi*2048 + kc);
            #pragma unroll
            for(int ng = 0; ng < 4; ng++) LDSM4(b[ng], smB + ng*2048 + kc);
            #pragma unroll
            for(int mi = 0; mi < 2; mi++)
            #pragma unroll
            for(int ng = 0; ng < 4; ng++){
                MMA16816(acc[mi][2*ng],   a[mi], b[ng][0], b[ng][2]);
                MMA16816(acc[mi][2*ng+1], a[mi], b[ng][1], b[ng][3]);
            }
        }
    }
    asm volatile("cp.async.wait_group 0;");
    __syncthreads();                              // mainloop smem dead; reuse for staging

    // -------- stage f32 tile (with bias, + silu for z-half) ------------------
    int grp = lane >> 2, c2 = (lane & 3) * 2;
    const bool zh = (MODE == 0) && (n0 >= DM);
    #pragma unroll
    for(int mi = 0; mi < 2; mi++){
        #pragma unroll
        for(int ni = 0; ni < 8; ni++){
            int rl = wm*32 + mi*16 + grp;
            int cl = wn*64 + ni*8 + c2;
            float b0 = __ldg(&bias[n0 + cl]), b1 = __ldg(&bias[n0 + cl + 1]);
            #pragma unroll
            for(int h = 0; h < 2; h++){
                float v0 = acc[mi][ni][2*h+0] + b0;
                float v1 = acc[mi][ni][2*h+1] + b1;
                if(zh){
                    v0 = v0 / (1.f + __expf(-v0));
                    v1 = v1 / (1.f + __expf(-v1));
                }
                float2 p; p.x = v0; p.y = v1;
                *(float2*)&epi[(rl + h*8)*EPI_PITCH + cl] = p;
            }
        }
    }
    __syncthreads();

    if(MODE == 0){
        // coalesced bf16 write-out: 128 rows x 16 x 16B
        __nv_bfloat16* dstb = zh ? g_zs : g_xproj;
        int colb = n0 - (zh ? DM : 0);
        #pragma unroll
        for(int i = 0; i < 8; i++){
            int idx = t + i*256;
            int r = idx >> 4, c = idx & 15;
            const float4 f0 = *(const float4*)&epi[r*EPI_PITCH + c*8];
            const float4 f1 = *(const float4*)&epi[r*EPI_PITCH + c*8 + 4];
            __nv_bfloat162 h0 = __floats2bfloat162_rn(f0.x, f0.y);
            __nv_bfloat162 h1 = __floats2bfloat162_rn(f0.z, f0.w);
            __nv_bfloat162 h2 = __floats2bfloat162_rn(f1.x, f1.y);
            __nv_bfloat162 h3 = __floats2bfloat162_rn(f1.z, f1.w);
            uint4 pk; pk.x = *(uint32_t*)&h0; pk.y = *(uint32_t*)&h1;
            pk.z = *(uint32_t*)&h2; pk.w = *(uint32_t*)&h3;
            *(uint4*)&dstb[(size_t)(m0 + r)*DM + colb + c*8] = pk;
        }
        // fused pass1: 4 chunk-end states per column (x-half only)
        if(!zh){
            int bb = m0 >> 11;                    // /LS
            int cbase = (m0 & (LS-1)) >> 5;       // /LC
            #pragma unroll
            for(int task = t; task < 512; task += 256){
                int cc = task >> 7, col = task & 127;
                int d = n0 + col;
                float Aa[DS], s[DS];
                const float4* A4 = reinterpret_cast<const float4*>(g_Abar + d*DS);
                #pragma unroll
                for(int j=0;j<4;j++){
                    float4 v=A4[j];
                    Aa[4*j]=v.x; Aa[4*j+1]=v.y; Aa[4*j+2]=v.z; Aa[4*j+3]=v.w;
                }
                #pragma unroll
                for(int n=0;n<DS;n++) s[n] = 0.f;
                const float* up = &epi[(cc*32)*EPI_PITCH + col];
                #pragma unroll 8
                for(int row = 0; row < LC; ++row){
                    float uv = up[row*EPI_PITCH];
                    #pragma unroll
                    for(int n=0;n<DS;n++) s[n] = fmaf(Aa[n], s[n], uv);
                }
                float4* F4 = reinterpret_cast<float4*>(
                    g_F + (size_t)(((cbase+cc)*NB + bb)*DM + d)*DS);
                #pragma unroll
                for(int j=0;j<4;j++){
                    float4 v; v.x=s[4*j]; v.y=s[4*j+1]; v.z=s[4*j+2]; v.w=s[4*j+3];
                    F4[j]=v;
                }
            }
        }
    } else {
        // coalesced f32 write-out with resid + clip: 128 rows x 32 float4
        #pragma unroll
        for(int i = 0; i < 16; i++){
            int idx = t + i*256;
            int r = idx >> 5, c = idx & 31;
            size_t gi = (size_t)(m0 + r)*DM + n0 + c*4;
            float4 v = *(const float4*)&epi[r*EPI_PITCH + c*4];
            float4 rv = *(const float4*)&resid[gi];
            v.x = fminf(fmaxf(v.x + rv.x, -10.f), 10.f);
            v.y = fminf(fmaxf(v.y + rv.y, -10.f), 10.f);
            v.z = fminf(fmaxf(v.z + rv.z, -10.f), 10.f);
            v.w = fminf(fmaxf(v.w + rv.w, -10.f), 10.f);
            *(float4*)&outp[gi] = v;
        }
    }
}

// ---------------- SSM two-level chunk scan ----------------
// pass2a: segment-local scans. Preload all 8 F values (independent loads,
// MLP=8), then register-only serial prefix -> latency no longer exposed.
__global__ void ssm_pass2a(){
    int t = threadIdx.x;
    int seg = blockIdx.x >> 8;                      // 8 segments x 256 blocks
    int i = ((blockIdx.x & 255) << 8) + t;          // element 0..NEL-1
    float Ap = g_Apow[i & (DM*DS - 1)];
    float f[SEGL];
    #pragma unroll
    for(int j = 0; j < SEGL; j++)
        f[j] = g_F[(size_t)(seg*SEGL + j)*NEL + i]; // 8 independent loads
    float s = 0.f;
    #pragma unroll
    for(int j = 0; j < SEGL; j++){
        g_Sin[(size_t)(seg*SEGL + j)*NEL + i] = s;  // segment-LOCAL incoming
        s = fmaf(Ap, s, f[j]);
    }
    g_Seg[(size_t)seg*NEL + i] = s;                 // segment end-state (zero init)
}

// pass2b: scan the 8 segment totals with decay Apow^SEGL (preloaded).
__global__ void ssm_pass2b(){
    int i = blockIdx.x*blockDim.x + threadIdx.x;
    float Ap = g_Apow[i & (DM*DS - 1)];
    float p2 = Ap*Ap, p4 = p2*p2, Ap8 = p4*p4;      // Apow^8
    float f[NSEG];
    #pragma unroll
    for(int seg = 0; seg < NSEG; seg++)
        f[seg] = g_Seg[(size_t)seg*NEL + i];        // 8 independent loads
    float s = 0.f;
    #pragma unroll
    for(int seg = 0; seg < NSEG; seg++){
        g_SegIn[(size_t)seg*NEL + i] = s;
        s = fmaf(Ap8, s, f[seg]);
    }
}

// pass3: replay chunk with true incoming state = local + Apow^j * SegIn.
__global__ void ssm_pass3(){
    __shared__ __align__(16) __nv_bfloat16 su[LC*128];   // 8KB u
    __shared__ __align__(16) __nv_bfloat16 sz[LC*128];   // 8KB silu(z)
    __shared__ __align__(16) __nv_bfloat16 so[LC*128];   // 8KB out
    int t = threadIdx.x;
    int c = blockIdx.y, b = blockIdx.z;
    int d = blockIdx.x*128 + t;
    size_t goff = (size_t)(b*LS + c*LC)*DM + blockIdx.x*128;
    const char* gu = (const char*)(g_xproj + goff);
    const char* gz = (const char*)(g_zs + goff);
    uint32_t sbu = (uint32_t)__cvta_generic_to_shared(su);
    uint32_t sbz = (uint32_t)__cvta_generic_to_shared(sz);
    #pragma unroll
    for(int i = 0; i < 4; i++){
        int idx = t + i*128;
        size_t go = (size_t)(idx >> 4)*(DM*2) + (idx & 15)*16;
        cp16(sbu + (uint32_t)idx*16, gu + go);
        cp16(sbz + (uint32_t)idx*16, gz + go);
    }
    asm volatile("cp.async.commit_group;");

    int seg = c >> 3, jj = c & 7;
    size_t eoff = (size_t)(b*DM + d)*DS;
    float Aa[DS], cb[DS], s[DS];
    const float4* A4 = reinterpret_cast<const float4*>(g_Abar + d*DS);
    const float4* C4 = reinterpret_cast<const float4*>(g_cbdt + d*DS);
    const float4* P4 = reinterpret_cast<const float4*>(g_Apow + d*DS);
    const float4* S4 = reinterpret_cast<const float4*>(g_Sin   + (size_t)c*NEL   + eoff);
    const float4* G4 = reinterpret_cast<const float4*>(g_SegIn + (size_t)seg*NEL + eoff);
    #pragma unroll
    for(int j=0;j<4;j++){
        float4 va=A4[j]; Aa[4*j]=va.x; Aa[4*j+1]=va.y; Aa[4*j+2]=va.z; Aa[4*j+3]=va.w;
        float4 vc=C4[j]; cb[4*j]=vc.x; cb[4*j+1]=vc.y; cb[4*j+2]=vc.z; cb[4*j+3]=vc.w;
        float4 vs=S4[j]; float4 vg=G4[j]; float4 vp=P4[j];
        float pw[4];
        pw[0]=vp.x; pw[1]=vp.y; pw[2]=vp.z; pw[3]=vp.w;
        float loc[4] = {vs.x, vs.y, vs.z, vs.w};
        float gin[4] = {vg.x, vg.y, vg.z, vg.w};
        #pragma unroll
        for(int q=0;q<4;q++){
            float p1 = pw[q], p2 = p1*p1, p4v = p2*p2;
            float apj = 1.f;
            if(jj & 1) apj *= p1;
            if(jj & 2) apj *= p2;
            if(jj & 4) apj *= p4v;
            s[4*j+q] = fmaf(apj, gin[q], loc[q]);
        }
    }
    asm volatile("cp.async.wait_group 0;");
    __syncthreads();
    #pragma unroll 4
    for(int tt = 0; tt < LC; ++tt){
        float uv = __bfloat162float(su[tt*128 + t]);
        #pragma unroll
        for(int n=0;n<DS;n++) s[n] = fmaf(Aa[n], s[n], uv);
        float y = 0.f;
        #pragma unroll
        for(int n=0;n<DS;n++) y = fmaf(cb[n], s[n], y);
        float zv = __bfloat162float(sz[tt*128 + t]);
        so[tt*128 + t] = __float2bfloat16_rn(y * zv);
    }
    __syncthreads();
    char* gg = (char*)(g_gated + goff);
    #pragma unroll
    for(int i = 0; i < 4; i++){                 // coalesced 16B stores
        int idx = t + i*128;
        *reinterpret_cast<uint4*>(gg + (size_t)(idx >> 4)*(DM*2) + (idx & 15)*16)
            = *reinterpret_cast<const uint4*>(reinterpret_cast<const char*>(so) + idx*16);
    }
}

// ---------------- launch ----------------
extern "C" void kernel_launch(void* const* d_in, const int* in_sizes, int n_in,
                              void* d_out, int out_size){
    const float* x      = (const float*)d_in[0];
    const float* A_log  = (const float*)d_in[1];
    const float* Bp     = (const float*)d_in[2];
    const float* Cp     = (const float*)d_in[3];
    const float* log_dt = (const float*)d_in[4];
    const float* in_w   = (const float*)d_in[5];
    const float* in_b   = (const float*)d_in[6];
    const float* out_w  = (const float*)d_in[7];
    const float* out_b  = (const float*)d_in[8];
    const float* ln_g   = (const float*)d_in[9];
    const float* ln_b   = (const float*)d_in[10];
    float* outp = (float*)d_out;

    cudaFuncSetAttribute(gemm_hmma<0>, cudaFuncAttributeMaxDynamicSharedMemorySize, GEMM_SMEM);
    cudaFuncSetAttribute(gemm_hmma<1>, cudaFuncAttributeMaxDynamicSharedMemorySize, GEMM_SMEM);

    prep_kernel<<<512, 256>>>(in_w, out_w, A_log, Bp, Cp, log_dt);
    ln_kernel<<<MR, 256>>>(x, ln_g, ln_b);
    gemm_hmma<0><<<dim3(2*DM/128, MR/128), 256, GEMM_SMEM>>>(in_b, nullptr, nullptr);
    ssm_pass2a<<<NSEG*256, 256>>>();
    ssm_pass2b<<<NEL/256, 256>>>();
    ssm_pass3<<<dim3(DM/128, NCH, NB), 128>>>();
    gemm_hmma<1><<<dim3(DM/128, MR/128), 256, GEMM_SMEM>>>(out_b, x, outp);
}